// round 3
// baseline (speedup 1.0000x reference)
#include <cuda_runtime.h>
#include <cuda_bf16.h>

// Problem constants
#define B   16
#define C   64
#define H   64
#define W   64
#define HID 128
#define G4  (4*HID)   // 512

// Scratch (device globals — no allocation allowed)
__device__ float g_i2h[H * B * W * G4];     // layout (h, b, w, d) : 134 MB
__device__ float g_Wit[3 * C * G4];         // (c*3+k, d)          : Wi transposed
__device__ float g_Wht4[HID * G4];          // float4 blocks: [(c/4)*512 + d] = Wh[d][4c..4c+3]

__device__ __forceinline__ float sigf(float x) {
    return 1.0f / (1.0f + __expf(-x));
}

// ---------------------------------------------------------------------------
// Prep: transpose Wi -> Wit (d contiguous), Wh -> Wht4 (float4 per d, c-block major)
// ---------------------------------------------------------------------------
__global__ void prep_kernel(const float* __restrict__ Wi,
                            const float* __restrict__ Wh) {
    int idx = blockIdx.x * blockDim.x + threadIdx.x;
    if (idx < G4 * C * 3) {              // 98304
        int d = idx / (C * 3);
        int r = idx % (C * 3);           // r = c*3 + k
        g_Wit[r * G4 + d] = Wi[idx];
    }
    if (idx < G4 * HID) {                // 65536
        int d = idx / HID;
        int c = idx % HID;
        // float4 element (cb = c>>2, lane d, component c&3)
        g_Wht4[(((c >> 2) * G4) + d) * 4 + (c & 3)] = Wh[idx];
    }
}

// ---------------------------------------------------------------------------
// Conv 1x3: i2h[h,b,w,d] = bi[d] + sum_c sum_k Wi[d,c,0,k] * x[b,c,h,w+k-1]
// One block per (b,h). 512 threads = one thread per output channel d.
// x row tile in smem (broadcast reads); 64 w-accumulators in registers.
// ---------------------------------------------------------------------------
__global__ __launch_bounds__(512, 1)
void conv_kernel(const float* __restrict__ x,
                 const float* __restrict__ bi) {
    int bh = blockIdx.x;
    int b  = bh >> 6;          // 0..15
    int hr = bh & 63;          // 0..63

    __shared__ float xs[C][W + 2];   // halo at w=0 and w=65

    int tid = threadIdx.x;

    // load x[b, :, hr, :] into smem (coalesced)
    for (int i = tid; i < C * W; i += 512) {
        int c = i >> 6;
        int w = i & 63;
        xs[c][w + 1] = x[(((b * C) + c) * H + hr) * W + w];
    }
    if (tid < C) {
        xs[tid][0]     = 0.0f;
        xs[tid][W + 1] = 0.0f;
    }
    __syncthreads();

    int d = tid;
    float bias = bi[d];

    float acc[W];
    #pragma unroll
    for (int w = 0; w < W; ++w) acc[w] = bias;

    for (int c = 0; c < C; ++c) {
        float w0 = g_Wit[(c * 3 + 0) * G4 + d];
        float w1 = g_Wit[(c * 3 + 1) * G4 + d];
        float w2 = g_Wit[(c * 3 + 2) * G4 + d];
        float xm = xs[c][0];
        float x0 = xs[c][1];
        #pragma unroll
        for (int w = 0; w < W; ++w) {
            float xp = xs[c][w + 2];
            acc[w] += w0 * xm;
            acc[w] += w1 * x0;
            acc[w] += w2 * xp;
            xm = x0;
            x0 = xp;
        }
    }

    // store: (h, b, w, d) layout — coalesced across d
    float* ob = g_i2h + (((hr * B) + b) * W) * G4 + d;
    #pragma unroll 8
    for (int w = 0; w < W; ++w) {
        ob[w * G4] = acc[w];
    }
}

// ---------------------------------------------------------------------------
// Row-LSTM scan. 128 blocks x 512 threads; block owns 8 consecutive w columns
// of one batch b. Runs all 64 H-steps. h state in smem, c state in registers.
// Per step: thread d computes gates[d] for its 8 columns (dot over 128 hid),
// smem exchange, then 2 (col,k) cell updates per thread.
// ---------------------------------------------------------------------------
__global__ __launch_bounds__(512, 1)
void lstm_kernel(const float* __restrict__ bh,
                 float* __restrict__ out) {
    int blk   = blockIdx.x;       // 0..127
    int b     = blk >> 3;         // 0..15
    int wbase = (blk & 7) * 8;    // 0,8,...,56

    // pad rows so smem bank = (4*j + k) mod 32 (a permutation over the warp)
    __shared__ float h_sm[8][132];
    __shared__ float gates_sm[8][516];

    int tid = threadIdx.x;
    int d   = tid;
    float bias = bh[d];

    for (int i = tid; i < 8 * 132; i += 512) ((float*)h_sm)[i] = 0.0f;

    // pair mapping p = k*8 + j ; thread handles p = tid and p = tid + 512
    int k0 = tid >> 3, j0 = tid & 7;
    int k1 = (tid + 512) >> 3, j1 = tid & 7;   // j identical, k offset by 64
    float cst0 = 0.0f, cst1 = 0.0f;

    __syncthreads();

    const float4* __restrict__ Wht4 = (const float4*)g_Wht4;

    for (int hr = 0; hr < H; ++hr) {
        // ---- gates: i2h + bh + Wh @ h ----
        float acc[8];
        const float* i2h_base = g_i2h + ((((hr * B) + b) * W) + wbase) * G4 + d;
        #pragma unroll
        for (int j = 0; j < 8; ++j) acc[j] = i2h_base[j * G4] + bias;

        #pragma unroll 4
        for (int cb = 0; cb < HID / 4; ++cb) {
            float4 wv = Wht4[cb * G4 + d];     // coalesced LDG.128 (L2-resident)
            #pragma unroll
            for (int j = 0; j < 8; ++j) {
                float4 hv = *(const float4*)&h_sm[j][cb * 4];  // broadcast LDS.128
                acc[j] += wv.x * hv.x;
                acc[j] += wv.y * hv.y;
                acc[j] += wv.z * hv.z;
                acc[j] += wv.w * hv.w;
            }
        }

        #pragma unroll
        for (int j = 0; j < 8; ++j) gates_sm[j][d] = acc[j];
        __syncthreads();

        // ---- cell update: 2 (col,k) pairs per thread ----
        {
            float ig = gates_sm[j0][k0];
            float fg = gates_sm[j0][k0 + 128];
            float og = gates_sm[j0][k0 + 256];
            float gg = gates_sm[j0][k0 + 384];
            cst0 = sigf(fg) * cst0 + sigf(ig) * tanhf(gg);
            float hv = sigf(og) * tanhf(cst0);
            h_sm[j0][k0] = hv;
            out[(((b * HID) + k0) * H + hr) * W + (wbase + j0)] = hv;
        }
        {
            float ig = gates_sm[j1][k1];
            float fg = gates_sm[j1][k1 + 128];
            float og = gates_sm[j1][k1 + 256];
            float gg = gates_sm[j1][k1 + 384];
            cst1 = sigf(fg) * cst1 + sigf(ig) * tanhf(gg);
            float hv = sigf(og) * tanhf(cst1);
            h_sm[j1][k1] = hv;
            out[(((b * HID) + k1) * H + hr) * W + (wbase + j1)] = hv;
        }
        __syncthreads();
    }
}

// ---------------------------------------------------------------------------
extern "C" void kernel_launch(void* const* d_in, const int* in_sizes, int n_in,
                              void* d_out, int out_size) {
    const float* x  = (const float*)d_in[0];
    const float* Wi = (const float*)d_in[1];
    const float* bi = (const float*)d_in[2];
    const float* Wh = (const float*)d_in[3];
    const float* bh = (const float*)d_in[4];
    float* out = (float*)d_out;

    prep_kernel<<<384, 256>>>(Wi, Wh);
    conv_kernel<<<B * H, 512>>>(x, bi);
    lstm_kernel<<<128, 512>>>(bh, out);
}

// round 5
// speedup vs baseline: 1.2560x; 1.2560x over previous
#include <cuda_runtime.h>
#include <cuda_bf16.h>
#include <cstdint>

// Problem constants
#define B_   16
#define C_   64
#define H_   64
#define W_   64
#define HID  128
#define G4   512          // 4*HID
#define KTOT 192          // C_*3

// ---------------------------------------------------------------------------
// Scratch (device globals — no allocation allowed)
// ---------------------------------------------------------------------------
__device__ float g_i2h[H_ * B_ * W_ * G4];          // (h, b, w, d) : 134 MB
__device__ float g_Wht4[HID * G4];                  // float4 blocks for lstm
// B pack: [kc][part][d][kk]  (6 chunks x 2 parts x 512 x 32 bf16) = 384KB
__device__ __nv_bfloat16 g_Bt[6 * 2 * G4 * 32];

__device__ __forceinline__ float sigf(float x) {
    return 1.0f / (1.0f + __expf(-x));
}

__device__ __forceinline__ uint32_t smem_u32(const void* p) {
    uint32_t a;
    asm("{ .reg .u64 t; cvta.to.shared.u64 t, %1; cvt.u32.u64 %0, t; }" : "=r"(a) : "l"(p));
    return a;
}

// ---- baseline-PTX building blocks (sm_80-era: OK on plain compute_103) ----
__device__ __forceinline__ void ldmatrix4(uint32_t* r, uint32_t addr) {
    asm volatile("ldmatrix.sync.aligned.m8n8.x4.shared.b16 {%0,%1,%2,%3}, [%4];"
                 : "=r"(r[0]), "=r"(r[1]), "=r"(r[2]), "=r"(r[3]) : "r"(addr));
}
__device__ __forceinline__ void mma16816(float* d, const uint32_t* a, const uint32_t* b) {
    asm volatile("mma.sync.aligned.m16n8k16.row.col.f32.bf16.bf16.f32 "
                 "{%0,%1,%2,%3}, {%4,%5,%6,%7}, {%8,%9}, {%0,%1,%2,%3};"
                 : "+f"(d[0]), "+f"(d[1]), "+f"(d[2]), "+f"(d[3])
                 : "r"(a[0]), "r"(a[1]), "r"(a[2]), "r"(a[3]), "r"(b[0]), "r"(b[1]));
}
__device__ __forceinline__ void cp_async16(uint32_t dst, const void* src) {
    asm volatile("cp.async.cg.shared.global [%0], [%1], 16;" :: "r"(dst), "l"(src));
}
#define CP_COMMIT() asm volatile("cp.async.commit_group;" ::: "memory")

// ---------------------------------------------------------------------------
// Prep: split Wi into bf16 hi/lo packed chunks; build Wht4 for the lstm.
// g_Bt[((kc*2+p)*512 + d)*32 + kk],  k = c*3+kw = kc*32+kk
// ---------------------------------------------------------------------------
__global__ void prep_kernel(const float* __restrict__ Wi,
                            const float* __restrict__ Wh) {
    int idx = blockIdx.x * blockDim.x + threadIdx.x;
    if (idx < G4 * KTOT) {               // 98304
        int d = idx / KTOT;
        int k = idx % KTOT;
        int kc = k >> 5, kk = k & 31;
        float v = Wi[idx];
        __nv_bfloat16 hi = __float2bfloat16(v);
        __nv_bfloat16 lo = __float2bfloat16(v - __bfloat162float(hi));
        g_Bt[((kc * 2 + 0) * G4 + d) * 32 + kk] = hi;
        g_Bt[((kc * 2 + 1) * G4 + d) * 32 + kk] = lo;
    }
    if (idx < G4 * HID) {                // 65536
        int d = idx / HID;
        int c = idx % HID;
        g_Wht4[(((c >> 2) * G4) + d) * 4 + (c & 3)] = Wh[idx];
    }
}

// ---------------------------------------------------------------------------
// Conv as mma.sync bf16 GEMM with split-bf16 fp32 emulation (hh + hl + lh).
// CTA: one (hr,b) pair -> M=64 rows (w), N=512, K=192 in 6 chunks of 32.
// 8 warps: warp tile 32(m) x 128(n). A im2col in smem; B double-buffered
// via cp.async. Epilogue adds bi and writes g_i2h.
// ---------------------------------------------------------------------------
// smem layout (bytes):
//   A:  part p at p*25600,  row m stride 400 (192*2 data + pad)  -> 51200
//   B:  buf q at 51200 + q*81920, part p at +p*40960, row n stride 80
#define A_PART   25600
#define B_OFF    51200
#define B_BUF    81920
#define B_PART   40960
#define CONV_SMEM (B_OFF + 2 * B_BUF)   // 215040

__device__ __forceinline__ void conv_issue_chunk(char* smem, uint32_t sb, int kc, int tid) {
    const char* src = (const char*)g_Bt + (size_t)kc * 65536;
    uint32_t dstb = sb + B_OFF + (kc & 1) * B_BUF;
    #pragma unroll
    for (int it = 0; it < 16; ++it) {
        int i = tid + it * 256;                 // 0..4095, 16B each
        int p = i >> 11, rem = i & 2047;
        int n = rem >> 2, seg = rem & 3;
        cp_async16(dstb + p * B_PART + n * 80 + seg * 16, src + i * 16);
    }
    CP_COMMIT();
}

__global__ void __launch_bounds__(256, 1)
conv_mma_kernel(const float* __restrict__ x, const float* __restrict__ bi) {
    extern __shared__ char smem[];
    uint32_t sb = smem_u32(smem);
    int tid = threadIdx.x;
    int lane = tid & 31, wid = tid >> 5;
    int t = blockIdx.x;                  // 0..1023  (= hb index)
    int b = t & 15, hr = t >> 4;

    int wm = wid & 1;                    // m 32-block
    int nbase = (wid >> 1) * 128;        // n range

    // prefetch B chunk 0
    conv_issue_chunk(smem, sb, 0, tid);

    // build A (im2col + hi/lo split): rows m = w (0..63), cols k = c*3+kw
    for (int e = tid; e < 64 * KTOT; e += 256) {
        int m = e & 63, kg = e >> 6;
        int c = kg / 3, kk = kg - 3 * c;
        int wi = m + kk - 1;
        float v = (wi >= 0 && wi < W_) ? x[(((b * C_) + c) * H_ + hr) * W_ + wi] : 0.0f;
        __nv_bfloat16 hi = __float2bfloat16(v);
        __nv_bfloat16 lo = __float2bfloat16(v - __bfloat162float(hi));
        *(__nv_bfloat16*)(smem + 0 * A_PART + m * 400 + kg * 2) = hi;
        *(__nv_bfloat16*)(smem + 1 * A_PART + m * 400 + kg * 2) = lo;
    }

    float d[128];
    #pragma unroll
    for (int i = 0; i < 128; ++i) d[i] = 0.0f;

    int tgrp = lane >> 3, trow = lane & 7;
    // A fragment address pieces (row within CTA tile)
    uint32_t arow0 = (uint32_t)(wm * 32 + (tgrp & 1) * 8 + trow);
    uint32_t acol16 = (uint32_t)((tgrp >> 1) * 16);
    // B fragment address pieces
    uint32_t brow = (uint32_t)(nbase + (tgrp >> 1) * 8 + trow);
    uint32_t bk16 = (uint32_t)((tgrp & 1) * 16);

    for (int kc = 0; kc < 6; ++kc) {
        if (kc < 5) {
            conv_issue_chunk(smem, sb, kc + 1, tid);
            asm volatile("cp.async.wait_group 1;" ::: "memory");
        } else {
            asm volatile("cp.async.wait_group 0;" ::: "memory");
        }
        __syncthreads();

        uint32_t Bb = sb + B_OFF + (kc & 1) * B_BUF;

        #pragma unroll
        for (int ks = 0; ks < 2; ++ks) {
            uint32_t kbyteA = (uint32_t)((kc * 32 + ks * 16) * 2) + acol16;
            uint32_t a_hi[2][4], a_lo[2][4];
            #pragma unroll
            for (int ms = 0; ms < 2; ++ms) {
                uint32_t aaddr = sb + (arow0 + ms * 16) * 400 + kbyteA;
                ldmatrix4(a_hi[ms], aaddr);
                ldmatrix4(a_lo[ms], aaddr + A_PART);
            }
            uint32_t bkoff = (uint32_t)(ks * 32) + bk16;

            // pass hh + lh : B hi fragments reused from registers
            #pragma unroll
            for (int nbp = 0; nbp < 8; ++nbp) {
                uint32_t bb[4];
                ldmatrix4(bb, Bb + 0 * B_PART + (brow + nbp * 16) * 80 + bkoff);
                #pragma unroll
                for (int ms = 0; ms < 2; ++ms) {
                    mma16816(d + (ms * 16 + 2 * nbp + 0) * 4, a_hi[ms], bb + 0);
                    mma16816(d + (ms * 16 + 2 * nbp + 1) * 4, a_hi[ms], bb + 2);
                    mma16816(d + (ms * 16 + 2 * nbp + 0) * 4, a_lo[ms], bb + 0);
                    mma16816(d + (ms * 16 + 2 * nbp + 1) * 4, a_lo[ms], bb + 2);
                }
            }
            // pass hl : A hi x B lo
            #pragma unroll
            for (int nbp = 0; nbp < 8; ++nbp) {
                uint32_t bb[4];
                ldmatrix4(bb, Bb + 1 * B_PART + (brow + nbp * 16) * 80 + bkoff);
                #pragma unroll
                for (int ms = 0; ms < 2; ++ms) {
                    mma16816(d + (ms * 16 + 2 * nbp + 0) * 4, a_hi[ms], bb + 0);
                    mma16816(d + (ms * 16 + 2 * nbp + 1) * 4, a_hi[ms], bb + 2);
                }
            }
        }
        __syncthreads();
    }

    // ---- Epilogue: +bi, write g_i2h (row r = t*64 + m, col = gate d) ----
    int qg = lane >> 2, qt = lane & 3;
    #pragma unroll
    for (int ms = 0; ms < 2; ++ms) {
        #pragma unroll
        for (int nb = 0; nb < 16; ++nb) {
            int col = nbase + nb * 8 + qt * 2;
            float2 bv = *(const float2*)(bi + col);
            #pragma unroll
            for (int half = 0; half < 2; ++half) {
                int row = t * 64 + wm * 32 + ms * 16 + half * 8 + qg;
                float2 o;
                o.x = d[(ms * 16 + nb) * 4 + half * 2 + 0] + bv.x;
                o.y = d[(ms * 16 + nb) * 4 + half * 2 + 1] + bv.y;
                *(float2*)(g_i2h + (size_t)row * G4 + col) = o;
            }
        }
    }
}

// ---------------------------------------------------------------------------
// Row-LSTM scan (unchanged — known good). 128 blocks x 512 threads.
// ---------------------------------------------------------------------------
__global__ __launch_bounds__(512, 1)
void lstm_kernel(const float* __restrict__ bh,
                 float* __restrict__ out) {
    int blk   = blockIdx.x;
    int b     = blk >> 3;
    int wbase = (blk & 7) * 8;

    __shared__ float h_sm[8][132];
    __shared__ float gates_sm[8][516];

    int tid = threadIdx.x;
    int d   = tid;
    float bias = bh[d];

    for (int i = tid; i < 8 * 132; i += 512) ((float*)h_sm)[i] = 0.0f;

    int k0 = tid >> 3, j0 = tid & 7;
    int k1 = (tid + 512) >> 3, j1 = tid & 7;
    float cst0 = 0.0f, cst1 = 0.0f;

    __syncthreads();

    const float4* __restrict__ Wht4 = (const float4*)g_Wht4;

    for (int hr = 0; hr < H_; ++hr) {
        float acc[8];
        const float* i2h_base = g_i2h + ((((hr * B_) + b) * W_) + wbase) * G4 + d;
        #pragma unroll
        for (int j = 0; j < 8; ++j) acc[j] = i2h_base[j * G4] + bias;

        #pragma unroll 4
        for (int cb = 0; cb < HID / 4; ++cb) {
            float4 wv = Wht4[cb * G4 + d];
            #pragma unroll
            for (int j = 0; j < 8; ++j) {
                float4 hv = *(const float4*)&h_sm[j][cb * 4];
                acc[j] += wv.x * hv.x;
                acc[j] += wv.y * hv.y;
                acc[j] += wv.z * hv.z;
                acc[j] += wv.w * hv.w;
            }
        }

        #pragma unroll
        for (int j = 0; j < 8; ++j) gates_sm[j][d] = acc[j];
        __syncthreads();

        {
            float ig = gates_sm[j0][k0];
            float fg = gates_sm[j0][k0 + 128];
            float og = gates_sm[j0][k0 + 256];
            float gg = gates_sm[j0][k0 + 384];
            cst0 = sigf(fg) * cst0 + sigf(ig) * tanhf(gg);
            float hv = sigf(og) * tanhf(cst0);
            h_sm[j0][k0] = hv;
            out[(((b * HID) + k0) * H_ + hr) * W_ + (wbase + j0)] = hv;
        }
        {
            float ig = gates_sm[j1][k1];
            float fg = gates_sm[j1][k1 + 128];
            float og = gates_sm[j1][k1 + 256];
            float gg = gates_sm[j1][k1 + 384];
            cst1 = sigf(fg) * cst1 + sigf(ig) * tanhf(gg);
            float hv = sigf(og) * tanhf(cst1);
            h_sm[j1][k1] = hv;
            out[(((b * HID) + k1) * H_ + hr) * W_ + (wbase + j1)] = hv;
        }
        __syncthreads();
    }
}

// ---------------------------------------------------------------------------
extern "C" void kernel_launch(void* const* d_in, const int* in_sizes, int n_in,
                              void* d_out, int out_size) {
    const float* x  = (const float*)d_in[0];
    const float* Wi = (const float*)d_in[1];
    const float* bi = (const float*)d_in[2];
    const float* Wh = (const float*)d_in[3];
    const float* bh = (const float*)d_in[4];
    float* out = (float*)d_out;

    static bool attr_set = false;
    if (!attr_set) {
        cudaFuncSetAttribute(conv_mma_kernel, cudaFuncAttributeMaxDynamicSharedMemorySize, CONV_SMEM);
        attr_set = true;
    }

    prep_kernel<<<384, 256>>>(Wi, Wh);
    conv_mma_kernel<<<1024, 256, CONV_SMEM>>>(x, bi);
    lstm_kernel<<<128, 512>>>(bh, out);
}

// round 6
// speedup vs baseline: 1.3587x; 1.0818x over previous
#include <cuda_runtime.h>
#include <cuda_bf16.h>
#include <cstdint>

// Problem constants
#define B_   16
#define C_   64
#define H_   64
#define W_   64
#define HID  128
#define G4   512          // 4*HID
#define KTOT 192          // C_*3

// ---------------------------------------------------------------------------
// Scratch (device globals — no allocation allowed)
// ---------------------------------------------------------------------------
__device__ float g_i2h[H_ * B_ * W_ * G4];          // (h, b, w, d) : 134 MB
__device__ float g_Wht4[HID * G4];                  // float4 blocks for lstm
__device__ float g_bias[G4];                        // bi + bh (folded)
// B pack: [kc][part][d][kk]  (6 chunks x 2 parts x 512 x 32 bf16) = 384KB
__device__ __nv_bfloat16 g_Bt[6 * 2 * G4 * 32];

typedef unsigned long long ull;

__device__ __forceinline__ uint32_t smem_u32(const void* p) {
    uint32_t a;
    asm("{ .reg .u64 t; cvta.to.shared.u64 t, %1; cvt.u32.u64 %0, t; }" : "=r"(a) : "l"(p));
    return a;
}

// fast exact-ish sigmoid / tanh (MUFU ex2 + rcp, ~2^-20 rel err)
__device__ __forceinline__ float siga(float x) {
    float t;
    asm("ex2.approx.f32 %0, %1;" : "=f"(t) : "f"(-1.4426950408889634f * x));
    float r;
    asm("rcp.approx.f32 %0, %1;" : "=f"(r) : "f"(1.0f + t));
    return r;
}
__device__ __forceinline__ float tanhe(float x) { return 2.0f * siga(2.0f * x) - 1.0f; }

// packed f32x2 helpers (sm_100-family base PTX)
__device__ __forceinline__ ull pk2(float x, float y) {
    ull r; asm("mov.b64 %0, {%1,%2};" : "=l"(r) : "f"(x), "f"(y)); return r;
}
__device__ __forceinline__ void fma2(ull& d, ull a, ull b) {
    asm("fma.rn.f32x2 %0, %1, %2, %0;" : "+l"(d) : "l"(a), "l"(b));
}
__device__ __forceinline__ void unpk2(float& x, float& y, ull v) {
    asm("mov.b64 {%0,%1}, %2;" : "=f"(x), "=f"(y) : "l"(v));
}

// ---- baseline-PTX building blocks (sm_80-era: OK on plain compute_103) ----
__device__ __forceinline__ void ldmatrix4(uint32_t* r, uint32_t addr) {
    asm volatile("ldmatrix.sync.aligned.m8n8.x4.shared.b16 {%0,%1,%2,%3}, [%4];"
                 : "=r"(r[0]), "=r"(r[1]), "=r"(r[2]), "=r"(r[3]) : "r"(addr));
}
__device__ __forceinline__ void mma16816(float* d, const uint32_t* a, const uint32_t* b) {
    asm volatile("mma.sync.aligned.m16n8k16.row.col.f32.bf16.bf16.f32 "
                 "{%0,%1,%2,%3}, {%4,%5,%6,%7}, {%8,%9}, {%0,%1,%2,%3};"
                 : "+f"(d[0]), "+f"(d[1]), "+f"(d[2]), "+f"(d[3])
                 : "r"(a[0]), "r"(a[1]), "r"(a[2]), "r"(a[3]), "r"(b[0]), "r"(b[1]));
}
__device__ __forceinline__ void cp_async16(uint32_t dst, const void* src) {
    asm volatile("cp.async.cg.shared.global [%0], [%1], 16;" :: "r"(dst), "l"(src));
}
#define CP_COMMIT() asm volatile("cp.async.commit_group;" ::: "memory")

// ---------------------------------------------------------------------------
// Prep: split Wi into bf16 hi/lo packed chunks; build Wht4 + fused bias.
// ---------------------------------------------------------------------------
__global__ void prep_kernel(const float* __restrict__ Wi,
                            const float* __restrict__ Wh,
                            const float* __restrict__ bi,
                            const float* __restrict__ bh) {
    int idx = blockIdx.x * blockDim.x + threadIdx.x;
    if (idx < G4 * KTOT) {               // 98304
        int d = idx / KTOT;
        int k = idx % KTOT;
        int kc = k >> 5, kk = k & 31;
        float v = Wi[idx];
        __nv_bfloat16 hi = __float2bfloat16(v);
        __nv_bfloat16 lo = __float2bfloat16(v - __bfloat162float(hi));
        g_Bt[((kc * 2 + 0) * G4 + d) * 32 + kk] = hi;
        g_Bt[((kc * 2 + 1) * G4 + d) * 32 + kk] = lo;
    }
    if (idx < G4 * HID) {                // 65536
        int d = idx / HID;
        int c = idx % HID;
        g_Wht4[(((c >> 2) * G4) + d) * 4 + (c & 3)] = Wh[idx];
    }
    if (idx < G4) g_bias[idx] = bi[idx] + bh[idx];
}

// ---------------------------------------------------------------------------
// Conv as mma.sync bf16 GEMM with split-bf16 fp32 emulation (hh + hl + lh).
// Epilogue adds (bi + bh) and writes g_i2h.
// ---------------------------------------------------------------------------
#define A_PART   25600
#define B_OFF    51200
#define B_BUF    81920
#define B_PART   40960
#define CONV_SMEM (B_OFF + 2 * B_BUF)   // 215040

__device__ __forceinline__ void conv_issue_chunk(char* smem, uint32_t sb, int kc, int tid) {
    const char* src = (const char*)g_Bt + (size_t)kc * 65536;
    uint32_t dstb = sb + B_OFF + (kc & 1) * B_BUF;
    #pragma unroll
    for (int it = 0; it < 16; ++it) {
        int i = tid + it * 256;                 // 0..4095, 16B each
        int p = i >> 11, rem = i & 2047;
        int n = rem >> 2, seg = rem & 3;
        cp_async16(dstb + p * B_PART + n * 80 + seg * 16, src + i * 16);
    }
    CP_COMMIT();
}

__global__ void __launch_bounds__(256, 1)
conv_mma_kernel(const float* __restrict__ x) {
    extern __shared__ char smem[];
    uint32_t sb = smem_u32(smem);
    int tid = threadIdx.x;
    int lane = tid & 31, wid = tid >> 5;
    int t = blockIdx.x;                  // 0..1023  (= hb index)
    int b = t & 15, hr = t >> 4;

    int wm = wid & 1;                    // m 32-block
    int nbase = (wid >> 1) * 128;        // n range

    // prefetch B chunk 0
    conv_issue_chunk(smem, sb, 0, tid);

    // build A (im2col + hi/lo split): rows m = w (0..63), cols k = c*3+kw
    for (int e = tid; e < 64 * KTOT; e += 256) {
        int m = e & 63, kg = e >> 6;
        int c = kg / 3, kk = kg - 3 * c;
        int wi = m + kk - 1;
        float v = (wi >= 0 && wi < W_) ? x[(((b * C_) + c) * H_ + hr) * W_ + wi] : 0.0f;
        __nv_bfloat16 hi = __float2bfloat16(v);
        __nv_bfloat16 lo = __float2bfloat16(v - __bfloat162float(hi));
        *(__nv_bfloat16*)(smem + 0 * A_PART + m * 400 + kg * 2) = hi;
        *(__nv_bfloat16*)(smem + 1 * A_PART + m * 400 + kg * 2) = lo;
    }

    float d[128];
    #pragma unroll
    for (int i = 0; i < 128; ++i) d[i] = 0.0f;

    int tgrp = lane >> 3, trow = lane & 7;
    uint32_t arow0 = (uint32_t)(wm * 32 + (tgrp & 1) * 8 + trow);
    uint32_t acol16 = (uint32_t)((tgrp >> 1) * 16);
    uint32_t brow = (uint32_t)(nbase + (tgrp >> 1) * 8 + trow);
    uint32_t bk16 = (uint32_t)((tgrp & 1) * 16);

    for (int kc = 0; kc < 6; ++kc) {
        if (kc < 5) {
            conv_issue_chunk(smem, sb, kc + 1, tid);
            asm volatile("cp.async.wait_group 1;" ::: "memory");
        } else {
            asm volatile("cp.async.wait_group 0;" ::: "memory");
        }
        __syncthreads();

        uint32_t Bb = sb + B_OFF + (kc & 1) * B_BUF;

        #pragma unroll
        for (int ks = 0; ks < 2; ++ks) {
            uint32_t kbyteA = (uint32_t)((kc * 32 + ks * 16) * 2) + acol16;
            uint32_t a_hi[2][4], a_lo[2][4];
            #pragma unroll
            for (int ms = 0; ms < 2; ++ms) {
                uint32_t aaddr = sb + (arow0 + ms * 16) * 400 + kbyteA;
                ldmatrix4(a_hi[ms], aaddr);
                ldmatrix4(a_lo[ms], aaddr + A_PART);
            }
            uint32_t bkoff = (uint32_t)(ks * 32) + bk16;

            #pragma unroll
            for (int nbp = 0; nbp < 8; ++nbp) {
                uint32_t bb[4];
                ldmatrix4(bb, Bb + 0 * B_PART + (brow + nbp * 16) * 80 + bkoff);
                #pragma unroll
                for (int ms = 0; ms < 2; ++ms) {
                    mma16816(d + (ms * 16 + 2 * nbp + 0) * 4, a_hi[ms], bb + 0);
                    mma16816(d + (ms * 16 + 2 * nbp + 1) * 4, a_hi[ms], bb + 2);
                    mma16816(d + (ms * 16 + 2 * nbp + 0) * 4, a_lo[ms], bb + 0);
                    mma16816(d + (ms * 16 + 2 * nbp + 1) * 4, a_lo[ms], bb + 2);
                }
            }
            #pragma unroll
            for (int nbp = 0; nbp < 8; ++nbp) {
                uint32_t bb[4];
                ldmatrix4(bb, Bb + 1 * B_PART + (brow + nbp * 16) * 80 + bkoff);
                #pragma unroll
                for (int ms = 0; ms < 2; ++ms) {
                    mma16816(d + (ms * 16 + 2 * nbp + 0) * 4, a_hi[ms], bb + 0);
                    mma16816(d + (ms * 16 + 2 * nbp + 1) * 4, a_hi[ms], bb + 2);
                }
            }
        }
        __syncthreads();
    }

    // ---- Epilogue: +(bi+bh), write g_i2h ----
    int qg = lane >> 2, qt = lane & 3;
    #pragma unroll
    for (int ms = 0; ms < 2; ++ms) {
        #pragma unroll
        for (int nb = 0; nb < 16; ++nb) {
            int col = nbase + nb * 8 + qt * 2;
            float2 bv = *(const float2*)(g_bias + col);
            #pragma unroll
            for (int half = 0; half < 2; ++half) {
                int row = t * 64 + wm * 32 + ms * 16 + half * 8 + qg;
                float2 o;
                o.x = d[(ms * 16 + nb) * 4 + half * 2 + 0] + bv.x;
                o.y = d[(ms * 16 + nb) * 4 + half * 2 + 1] + bv.y;
                *(float2*)(g_i2h + (size_t)row * G4 + col) = o;
            }
        }
    }
}

// ---------------------------------------------------------------------------
// Row-LSTM scan with packed f32x2 FMA. 128 blocks x 512 threads;
// block owns 8 w columns of one batch b, runs all 64 H-steps.
// h state in smem as [hid][8] so the 8 col-accumulators pair into f32x2.
// i2h row for step hr+1 prefetched into registers during step hr's GEMM.
// ---------------------------------------------------------------------------
__global__ __launch_bounds__(512, 1)
void lstm_kernel(float* __restrict__ out) {
    int blk   = blockIdx.x;
    int b     = blk >> 3;
    int wbase = (blk & 7) * 8;

    __shared__ float h2_sm[HID][8];      // [hid c][col j]
    __shared__ float gates_sm[8][516];   // [col j][gate d], padded

    int tid = threadIdx.x;
    int d   = tid;

    for (int i = tid; i < HID * 8; i += 512) ((float*)h2_sm)[i] = 0.0f;

    int k0 = tid >> 3, j0 = tid & 7;
    int k1 = k0 + 64;
    float cst0 = 0.0f, cst1 = 0.0f;

    // prefetch i2h row 0
    float inext[8];
    {
        const float* p = g_i2h + ((size_t)((0 * B_ + b) * W_ + wbase)) * G4 + d;
        #pragma unroll
        for (int j = 0; j < 8; ++j) inext[j] = p[j * G4];
    }

    __syncthreads();

    const float4* __restrict__ Wht4 = (const float4*)g_Wht4;

    for (int hr = 0; hr < H_; ++hr) {
        // init accumulators from prefetched i2h (bias already folded in)
        ull acc2[4];
        #pragma unroll
        for (int p = 0; p < 4; ++p) acc2[p] = pk2(inext[2 * p], inext[2 * p + 1]);

        // prefetch next row's i2h (independent of recurrence; hides DRAM)
        {
            int hn = (hr < H_ - 1) ? hr + 1 : hr;
            const float* p = g_i2h + ((size_t)((hn * B_ + b) * W_ + wbase)) * G4 + d;
            #pragma unroll
            for (int j = 0; j < 8; ++j) inext[j] = p[j * G4];
        }

        // ---- gates += Wh @ h  (packed f32x2) ----
        #pragma unroll 8
        for (int cb = 0; cb < HID / 4; ++cb) {
            float4 wv = Wht4[cb * G4 + d];     // coalesced LDG.128 (L2-resident)
            #pragma unroll
            for (int cc = 0; cc < 4; ++cc) {
                float w = (cc == 0) ? wv.x : (cc == 1) ? wv.y : (cc == 2) ? wv.z : wv.w;
                ull wb = pk2(w, w);
                const ulonglong2* hv = (const ulonglong2*)&h2_sm[4 * cb + cc][0];
                ulonglong2 ha = hv[0];          // j0..j3  (broadcast LDS.128)
                ulonglong2 hb = hv[1];          // j4..j7
                fma2(acc2[0], ha.x, wb);
                fma2(acc2[1], ha.y, wb);
                fma2(acc2[2], hb.x, wb);
                fma2(acc2[3], hb.y, wb);
            }
        }

        // unpack to gates smem: gates_sm[j][d]
        #pragma unroll
        for (int p = 0; p < 4; ++p) {
            float a0, a1;
            unpk2(a0, a1, acc2[p]);
            gates_sm[2 * p + 0][d] = a0;
            gates_sm[2 * p + 1][d] = a1;
        }
        __syncthreads();

        // ---- cell update: 2 (col,k) pairs per thread ----
        {
            float ig = gates_sm[j0][k0];
            float fg = gates_sm[j0][k0 + 128];
            float og = gates_sm[j0][k0 + 256];
            float gg = gates_sm[j0][k0 + 384];
            cst0 = siga(fg) * cst0 + siga(ig) * tanhe(gg);
            float hv = siga(og) * tanhe(cst0);
            h2_sm[k0][j0] = hv;
            out[(((b * HID) + k0) * H_ + hr) * W_ + (wbase + j0)] = hv;
        }
        {
            float ig = gates_sm[j0][k1];
            float fg = gates_sm[j0][k1 + 128];
            float og = gates_sm[j0][k1 + 256];
            float gg = gates_sm[j0][k1 + 384];
            cst1 = siga(fg) * cst1 + siga(ig) * tanhe(gg);
            float hv = siga(og) * tanhe(cst1);
            h2_sm[k1][j0] = hv;
            out[(((b * HID) + k1) * H_ + hr) * W_ + (wbase + j0)] = hv;
        }
        __syncthreads();
    }
}

// ---------------------------------------------------------------------------
extern "C" void kernel_launch(void* const* d_in, const int* in_sizes, int n_in,
                              void* d_out, int out_size) {
    const float* x  = (const float*)d_in[0];
    const float* Wi = (const float*)d_in[1];
    const float* bi = (const float*)d_in[2];
    const float* Wh = (const float*)d_in[3];
    const float* bh = (const float*)d_in[4];
    float* out = (float*)d_out;

    static bool attr_set = false;
    if (!attr_set) {
        cudaFuncSetAttribute(conv_mma_kernel, cudaFuncAttributeMaxDynamicSharedMemorySize, CONV_SMEM);
        attr_set = true;
    }

    prep_kernel<<<384, 256>>>(Wi, Wh, bi, bh);
    conv_mma_kernel<<<1024, 256, CONV_SMEM>>>(x);
    lstm_kernel<<<128, 512>>>(out);
}

// round 10
// speedup vs baseline: 1.5480x; 1.1393x over previous
#include <cuda_runtime.h>
#include <cuda_bf16.h>
#include <cstdint>

// Problem constants
#define B_   16
#define C_   64
#define H_   64
#define W_   64
#define HID  128
#define G4   512          // 4*HID
#define KTOT 192          // C_*3

// ---------------------------------------------------------------------------
// Scratch (device globals — no allocation allowed)
// ---------------------------------------------------------------------------
__device__ float g_i2h[H_ * B_ * W_ * G4];          // (h, b, w, d) : 134 MB
__device__ float g_Wht4[HID * G4];                  // float4 blocks for lstm
__device__ float g_bias[G4];                        // bi + bh (folded)
// B pack: [kc][part][d][kk]  (6 chunks x 2 parts x 512 x 32 bf16) = 384KB
__device__ __nv_bfloat16 g_Bt[6 * 2 * G4 * 32];

typedef unsigned long long ull;

__device__ __forceinline__ uint32_t smem_u32(const void* p) {
    uint32_t a;
    asm("{ .reg .u64 t; cvta.to.shared.u64 t, %1; cvt.u32.u64 %0, t; }" : "=r"(a) : "l"(p));
    return a;
}

// fast exact-ish sigmoid / tanh (MUFU ex2 + rcp, ~2^-20 rel err)
__device__ __forceinline__ float siga(float x) {
    float t;
    asm("ex2.approx.f32 %0, %1;" : "=f"(t) : "f"(-1.4426950408889634f * x));
    float r;
    asm("rcp.approx.f32 %0, %1;" : "=f"(r) : "f"(1.0f + t));
    return r;
}
__device__ __forceinline__ float tanhe(float x) { return 2.0f * siga(2.0f * x) - 1.0f; }

// packed f32x2 helpers (sm_100-family base PTX)
__device__ __forceinline__ ull pk2(float x, float y) {
    ull r; asm("mov.b64 %0, {%1,%2};" : "=l"(r) : "f"(x), "f"(y)); return r;
}
__device__ __forceinline__ void fma2(ull& d, ull a, ull b) {
    asm("fma.rn.f32x2 %0, %1, %2, %0;" : "+l"(d) : "l"(a), "l"(b));
}
__device__ __forceinline__ void unpk2(float& x, float& y, ull v) {
    asm("mov.b64 {%0,%1}, %2;" : "=f"(x), "=f"(y) : "l"(v));
}

// ---- baseline-PTX building blocks (sm_80-era: OK on plain compute_103) ----
__device__ __forceinline__ void ldmatrix4(uint32_t* r, uint32_t addr) {
    asm volatile("ldmatrix.sync.aligned.m8n8.x4.shared.b16 {%0,%1,%2,%3}, [%4];"
                 : "=r"(r[0]), "=r"(r[1]), "=r"(r[2]), "=r"(r[3]) : "r"(addr));
}
__device__ __forceinline__ void mma16816(float* d, const uint32_t* a, const uint32_t* b) {
    asm volatile("mma.sync.aligned.m16n8k16.row.col.f32.bf16.bf16.f32 "
                 "{%0,%1,%2,%3}, {%4,%5,%6,%7}, {%8,%9}, {%0,%1,%2,%3};"
                 : "+f"(d[0]), "+f"(d[1]), "+f"(d[2]), "+f"(d[3])
                 : "r"(a[0]), "r"(a[1]), "r"(a[2]), "r"(a[3]), "r"(b[0]), "r"(b[1]));
}
__device__ __forceinline__ void cp_async16(uint32_t dst, const void* src) {
    asm volatile("cp.async.cg.shared.global [%0], [%1], 16;" :: "r"(dst), "l"(src));
}
#define CP_COMMIT() asm volatile("cp.async.commit_group;" ::: "memory")

// ---------------------------------------------------------------------------
// Prep: split Wi into bf16 hi/lo packed chunks; build Wht4 + fused bias.
// ---------------------------------------------------------------------------
__global__ void prep_kernel(const float* __restrict__ Wi,
                            const float* __restrict__ Wh,
                            const float* __restrict__ bi,
                            const float* __restrict__ bh) {
    int idx = blockIdx.x * blockDim.x + threadIdx.x;
    if (idx < G4 * KTOT) {               // 98304
        int d = idx / KTOT;
        int k = idx % KTOT;
        int kc = k >> 5, kk = k & 31;
        float v = Wi[idx];
        __nv_bfloat16 hi = __float2bfloat16(v);
        __nv_bfloat16 lo = __float2bfloat16(v - __bfloat162float(hi));
        g_Bt[((kc * 2 + 0) * G4 + d) * 32 + kk] = hi;
        g_Bt[((kc * 2 + 1) * G4 + d) * 32 + kk] = lo;
    }
    if (idx < G4 * HID) {                // 65536
        int d = idx / HID;
        int c = idx % HID;
        g_Wht4[(((c >> 2) * G4) + d) * 4 + (c & 3)] = Wh[idx];
    }
    if (idx < G4) g_bias[idx] = bi[idx] + bh[idx];
}

// ---------------------------------------------------------------------------
// Conv as mma.sync bf16 GEMM with split-bf16 fp32 emulation (hh + hl + lh).
// (unchanged from R6 — passing)
// ---------------------------------------------------------------------------
#define A_PART   25600
#define B_OFF    51200
#define B_BUF    81920
#define B_PART   40960
#define CONV_SMEM (B_OFF + 2 * B_BUF)   // 215040

__device__ __forceinline__ void conv_issue_chunk(char* smem, uint32_t sb, int kc, int tid) {
    const char* src = (const char*)g_Bt + (size_t)kc * 65536;
    uint32_t dstb = sb + B_OFF + (kc & 1) * B_BUF;
    #pragma unroll
    for (int it = 0; it < 16; ++it) {
        int i = tid + it * 256;                 // 0..4095, 16B each
        int p = i >> 11, rem = i & 2047;
        int n = rem >> 2, seg = rem & 3;
        cp_async16(dstb + p * B_PART + n * 80 + seg * 16, src + i * 16);
    }
    CP_COMMIT();
}

__global__ void __launch_bounds__(256, 1)
conv_mma_kernel(const float* __restrict__ x) {
    extern __shared__ char smem[];
    uint32_t sb = smem_u32(smem);
    int tid = threadIdx.x;
    int lane = tid & 31, wid = tid >> 5;
    int t = blockIdx.x;                  // 0..1023  (= hb index)
    int b = t & 15, hr = t >> 4;

    int wm = wid & 1;                    // m 32-block
    int nbase = (wid >> 1) * 128;        // n range

    conv_issue_chunk(smem, sb, 0, tid);

    for (int e = tid; e < 64 * KTOT; e += 256) {
        int m = e & 63, kg = e >> 6;
        int c = kg / 3, kk = kg - 3 * c;
        int wi = m + kk - 1;
        float v = (wi >= 0 && wi < W_) ? x[(((b * C_) + c) * H_ + hr) * W_ + wi] : 0.0f;
        __nv_bfloat16 hi = __float2bfloat16(v);
        __nv_bfloat16 lo = __float2bfloat16(v - __bfloat162float(hi));
        *(__nv_bfloat16*)(smem + 0 * A_PART + m * 400 + kg * 2) = hi;
        *(__nv_bfloat16*)(smem + 1 * A_PART + m * 400 + kg * 2) = lo;
    }

    float d[128];
    #pragma unroll
    for (int i = 0; i < 128; ++i) d[i] = 0.0f;

    int tgrp = lane >> 3, trow = lane & 7;
    uint32_t arow0 = (uint32_t)(wm * 32 + (tgrp & 1) * 8 + trow);
    uint32_t acol16 = (uint32_t)((tgrp >> 1) * 16);
    uint32_t brow = (uint32_t)(nbase + (tgrp >> 1) * 8 + trow);
    uint32_t bk16 = (uint32_t)((tgrp & 1) * 16);

    for (int kc = 0; kc < 6; ++kc) {
        if (kc < 5) {
            conv_issue_chunk(smem, sb, kc + 1, tid);
            asm volatile("cp.async.wait_group 1;" ::: "memory");
        } else {
            asm volatile("cp.async.wait_group 0;" ::: "memory");
        }
        __syncthreads();

        uint32_t Bb = sb + B_OFF + (kc & 1) * B_BUF;

        #pragma unroll
        for (int ks = 0; ks < 2; ++ks) {
            uint32_t kbyteA = (uint32_t)((kc * 32 + ks * 16) * 2) + acol16;
            uint32_t a_hi[2][4], a_lo[2][4];
            #pragma unroll
            for (int ms = 0; ms < 2; ++ms) {
                uint32_t aaddr = sb + (arow0 + ms * 16) * 400 + kbyteA;
                ldmatrix4(a_hi[ms], aaddr);
                ldmatrix4(a_lo[ms], aaddr + A_PART);
            }
            uint32_t bkoff = (uint32_t)(ks * 32) + bk16;

            #pragma unroll
            for (int nbp = 0; nbp < 8; ++nbp) {
                uint32_t bb[4];
                ldmatrix4(bb, Bb + 0 * B_PART + (brow + nbp * 16) * 80 + bkoff);
                #pragma unroll
                for (int ms = 0; ms < 2; ++ms) {
                    mma16816(d + (ms * 16 + 2 * nbp + 0) * 4, a_hi[ms], bb + 0);
                    mma16816(d + (ms * 16 + 2 * nbp + 1) * 4, a_hi[ms], bb + 2);
                    mma16816(d + (ms * 16 + 2 * nbp + 0) * 4, a_lo[ms], bb + 0);
                    mma16816(d + (ms * 16 + 2 * nbp + 1) * 4, a_lo[ms], bb + 2);
                }
            }
            #pragma unroll
            for (int nbp = 0; nbp < 8; ++nbp) {
                uint32_t bb[4];
                ldmatrix4(bb, Bb + 1 * B_PART + (brow + nbp * 16) * 80 + bkoff);
                #pragma unroll
                for (int ms = 0; ms < 2; ++ms) {
                    mma16816(d + (ms * 16 + 2 * nbp + 0) * 4, a_hi[ms], bb + 0);
                    mma16816(d + (ms * 16 + 2 * nbp + 1) * 4, a_hi[ms], bb + 2);
                }
            }
        }
        __syncthreads();
    }

    int qg = lane >> 2, qt = lane & 3;
    #pragma unroll
    for (int ms = 0; ms < 2; ++ms) {
        #pragma unroll
        for (int nb = 0; nb < 16; ++nb) {
            int col = nbase + nb * 8 + qt * 2;
            float2 bv = *(const float2*)(g_bias + col);
            #pragma unroll
            for (int half = 0; half < 2; ++half) {
                int row = t * 64 + wm * 32 + ms * 16 + half * 8 + qg;
                float2 o;
                o.x = d[(ms * 16 + nb) * 4 + half * 2 + 0] + bv.x;
                o.y = d[(ms * 16 + nb) * 4 + half * 2 + 1] + bv.y;
                *(float2*)(g_i2h + (size_t)row * G4 + col) = o;
            }
        }
    }
}

// ---------------------------------------------------------------------------
// Row-LSTM scan, f32x2, with Wh resident on-SM:
//   c-blocks 0..19 (c=0..79)  -> smem (160KB, loaded once)
//   c-blocks 20..31 (c=80..127) -> registers (12 float4/thread)
// Eliminates the 2.1GB per-run L2 weight restream of R6.
// ---------------------------------------------------------------------------
#define CB_SM   20
#define CB_RG   12
#define LSTM_WH_BYTES  (CB_SM * G4 * 16)                   // 163840
#define LSTM_H_OFF     LSTM_WH_BYTES                       // h2: 128*8 floats
#define LSTM_G_OFF     (LSTM_H_OFF + HID * 8 * 4)          // gates: 8*516 floats
#define LSTM_SMEM      (LSTM_G_OFF + 8 * 516 * 4)          // 184448

__global__ __launch_bounds__(512, 1)
void lstm_kernel(float* __restrict__ out) {
    extern __shared__ char smem[];
    float4* wh4 = (float4*)smem;                           // [cb*512 + d]
    float*  h2  = (float*)(smem + LSTM_H_OFF);             // [c*8 + j]
    float*  gt  = (float*)(smem + LSTM_G_OFF);             // [j*516 + d]

    int blk   = blockIdx.x;
    int b     = blk >> 3;
    int wbase = (blk & 7) * 8;

    int tid = threadIdx.x;
    int d   = tid;

    // load smem half of Wh (first 20 cb of g_Wht4) — one-time
    {
        const float4* src = (const float4*)g_Wht4;
        #pragma unroll
        for (int i = tid; i < CB_SM * G4; i += 512) wh4[i] = src[i];
    }
    // register half: thread d holds cb 20..31 (c = 80..127)
    float4 wr[CB_RG];
    {
        const float4* src = (const float4*)g_Wht4;
        #pragma unroll
        for (int i = 0; i < CB_RG; ++i) wr[i] = src[(CB_SM + i) * G4 + d];
    }

    for (int i = tid; i < HID * 8; i += 512) h2[i] = 0.0f;

    int k0 = tid >> 3, j0 = tid & 7;
    int k1 = k0 + 64;
    float cst0 = 0.0f, cst1 = 0.0f;

    // prefetch i2h row 0
    float inext[8];
    {
        const float* p = g_i2h + ((size_t)((0 * B_ + b) * W_ + wbase)) * G4 + d;
        #pragma unroll
        for (int j = 0; j < 8; ++j) inext[j] = p[j * G4];
    }

    __syncthreads();

    for (int hr = 0; hr < H_; ++hr) {
        ull acc2[4];
        #pragma unroll
        for (int p = 0; p < 4; ++p) acc2[p] = pk2(inext[2 * p], inext[2 * p + 1]);

        // prefetch next row's i2h (hides DRAM latency under the GEMM)
        {
            int hn = (hr < H_ - 1) ? hr + 1 : hr;
            const float* p = g_i2h + ((size_t)((hn * B_ + b) * W_ + wbase)) * G4 + d;
            #pragma unroll
            for (int j = 0; j < 8; ++j) inext[j] = p[j * G4];
        }

        // ---- gates += Wh @ h : smem-weight half (c = 0..79) ----
        #pragma unroll 5
        for (int cb = 0; cb < CB_SM; ++cb) {
            float4 wv = wh4[cb * G4 + d];          // LDS.128, conflict-free
            #pragma unroll
            for (int cc = 0; cc < 4; ++cc) {
                float w = (cc == 0) ? wv.x : (cc == 1) ? wv.y : (cc == 2) ? wv.z : wv.w;
                ull wb = pk2(w, w);
                const ulonglong2* hv = (const ulonglong2*)(h2 + (4 * cb + cc) * 8);
                ulonglong2 ha = hv[0];              // broadcast LDS.128
                ulonglong2 hb2 = hv[1];
                fma2(acc2[0], ha.x, wb);
                fma2(acc2[1], ha.y, wb);
                fma2(acc2[2], hb2.x, wb);
                fma2(acc2[3], hb2.y, wb);
            }
        }
        // ---- register-weight half (c = 80..127) ----
        #pragma unroll
        for (int i = 0; i < CB_RG; ++i) {
            float4 wv = wr[i];
            #pragma unroll
            for (int cc = 0; cc < 4; ++cc) {
                float w = (cc == 0) ? wv.x : (cc == 1) ? wv.y : (cc == 2) ? wv.z : wv.w;
                ull wb = pk2(w, w);
                const ulonglong2* hv = (const ulonglong2*)(h2 + (4 * (CB_SM + i) + cc) * 8);
                ulonglong2 ha = hv[0];
                ulonglong2 hb2 = hv[1];
                fma2(acc2[0], ha.x, wb);
                fma2(acc2[1], ha.y, wb);
                fma2(acc2[2], hb2.x, wb);
                fma2(acc2[3], hb2.y, wb);
            }
        }

        // unpack to gates smem: gt[j*516 + d]
        #pragma unroll
        for (int p = 0; p < 4; ++p) {
            float a0, a1;
            unpk2(a0, a1, acc2[p]);
            gt[(2 * p + 0) * 516 + d] = a0;
            gt[(2 * p + 1) * 516 + d] = a1;
        }
        __syncthreads();

        // ---- cell update: 2 (col,k) pairs per thread ----
        {
            float ig = gt[j0 * 516 + k0];
            float fg = gt[j0 * 516 + k0 + 128];
            float og = gt[j0 * 516 + k0 + 256];
            float gg = gt[j0 * 516 + k0 + 384];
            cst0 = siga(fg) * cst0 + siga(ig) * tanhe(gg);
            float hv = siga(og) * tanhe(cst0);
            h2[k0 * 8 + j0] = hv;
            out[(((b * HID) + k0) * H_ + hr) * W_ + (wbase + j0)] = hv;
        }
        {
            float ig = gt[j0 * 516 + k1];
            float fg = gt[j0 * 516 + k1 + 128];
            float og = gt[j0 * 516 + k1 + 256];
            float gg = gt[j0 * 516 + k1 + 384];
            cst1 = siga(fg) * cst1 + siga(ig) * tanhe(gg);
            float hv = siga(og) * tanhe(cst1);
            h2[k1 * 8 + j0] = hv;
            out[(((b * HID) + k1) * H_ + hr) * W_ + (wbase + j0)] = hv;
        }
        __syncthreads();
    }
}

// ---------------------------------------------------------------------------
extern "C" void kernel_launch(void* const* d_in, const int* in_sizes, int n_in,
                              void* d_out, int out_size) {
    const float* x  = (const float*)d_in[0];
    const float* Wi = (const float*)d_in[1];
    const float* bi = (const float*)d_in[2];
    const float* Wh = (const float*)d_in[3];
    const float* bh = (const float*)d_in[4];
    float* out = (float*)d_out;

    static bool attr_set = false;
    if (!attr_set) {
        cudaFuncSetAttribute(conv_mma_kernel, cudaFuncAttributeMaxDynamicSharedMemorySize, CONV_SMEM);
        cudaFuncSetAttribute(lstm_kernel, cudaFuncAttributeMaxDynamicSharedMemorySize, LSTM_SMEM);
        attr_set = true;
    }

    prep_kernel<<<384, 256>>>(Wi, Wh, bi, bh);
    conv_mma_kernel<<<1024, 256, CONV_SMEM>>>(x);
    lstm_kernel<<<128, 512, LSTM_SMEM>>>(out);
}

// round 11
// speedup vs baseline: 2.5269x; 1.6323x over previous
#include <cuda_runtime.h>
#include <cuda_bf16.h>
#include <cstdint>

// Problem constants
#define B_   16
#define C_   64
#define H_   64
#define W_   64
#define HID  128
#define G4   512          // 4*HID
#define KTOT 192          // C_*3

// ---------------------------------------------------------------------------
// Scratch (device globals — no allocation allowed)
// ---------------------------------------------------------------------------
__device__ float g_i2h[H_ * B_ * W_ * G4];          // (h, b, w, d) : 134 MB
__device__ float g_bias[G4];                        // bi + bh (folded)
// conv B pack: [kc][part][d][kk]  (6 x 2 x 512 x 32 bf16) = 384KB
__device__ __nv_bfloat16 g_Bt[6 * 2 * G4 * 32];
// lstm Wh mma fragments (hi / lo bf16 pairs), PTX m16n8k16 A-fragment order:
// slot = ((((warp*2+mt)*8 + kt)*32) + lane)*4 + i
__device__ uint32_t g_fAhi[32768];                  // 128KB
__device__ uint32_t g_fAlo[32768];                  // 128KB

typedef unsigned long long ull;

__device__ __forceinline__ uint32_t smem_u32(const void* p) {
    uint32_t a;
    asm("{ .reg .u64 t; cvta.to.shared.u64 t, %1; cvt.u32.u64 %0, t; }" : "=r"(a) : "l"(p));
    return a;
}

// fast exact-ish sigmoid / tanh (MUFU ex2 + rcp, ~2^-20 rel err)
__device__ __forceinline__ float siga(float x) {
    float t;
    asm("ex2.approx.f32 %0, %1;" : "=f"(t) : "f"(-1.4426950408889634f * x));
    float r;
    asm("rcp.approx.f32 %0, %1;" : "=f"(r) : "f"(1.0f + t));
    return r;
}
__device__ __forceinline__ float tanhe(float x) { return 2.0f * siga(2.0f * x) - 1.0f; }

// ---- baseline-PTX building blocks (sm_80-era: OK on plain compute_103) ----
__device__ __forceinline__ void ldmatrix4(uint32_t* r, uint32_t addr) {
    asm volatile("ldmatrix.sync.aligned.m8n8.x4.shared.b16 {%0,%1,%2,%3}, [%4];"
                 : "=r"(r[0]), "=r"(r[1]), "=r"(r[2]), "=r"(r[3]) : "r"(addr));
}
__device__ __forceinline__ void mma16816(float* d, const uint32_t* a, const uint32_t* b) {
    asm volatile("mma.sync.aligned.m16n8k16.row.col.f32.bf16.bf16.f32 "
                 "{%0,%1,%2,%3}, {%4,%5,%6,%7}, {%8,%9}, {%0,%1,%2,%3};"
                 : "+f"(d[0]), "+f"(d[1]), "+f"(d[2]), "+f"(d[3])
                 : "r"(a[0]), "r"(a[1]), "r"(a[2]), "r"(a[3]), "r"(b[0]), "r"(b[1]));
}
__device__ __forceinline__ void cp_async16(uint32_t dst, const void* src) {
    asm volatile("cp.async.cg.shared.global [%0], [%1], 16;" :: "r"(dst), "l"(src));
}
#define CP_COMMIT() asm volatile("cp.async.commit_group;" ::: "memory")

__device__ __forceinline__ uint32_t pkbf(__nv_bfloat16 lo, __nv_bfloat16 hi) {
    return (uint32_t)__bfloat16_as_ushort(lo) | ((uint32_t)__bfloat16_as_ushort(hi) << 16);
}

// ---------------------------------------------------------------------------
// Prep: conv Wi hi/lo pack, lstm Wh mma fragments, fused bias.
// ---------------------------------------------------------------------------
__global__ void prep_kernel(const float* __restrict__ Wi,
                            const float* __restrict__ Wh,
                            const float* __restrict__ bi,
                            const float* __restrict__ bh) {
    int idx = blockIdx.x * blockDim.x + threadIdx.x;
    if (idx < G4 * KTOT) {               // 98304 : conv B tiles
        int d = idx / KTOT;
        int k = idx % KTOT;
        int kc = k >> 5, kk = k & 31;
        float v = Wi[idx];
        __nv_bfloat16 hi = __float2bfloat16(v);
        __nv_bfloat16 lo = __float2bfloat16(v - __bfloat162float(hi));
        g_Bt[((kc * 2 + 0) * G4 + d) * 32 + kk] = hi;
        g_Bt[((kc * 2 + 1) * G4 + d) * 32 + kk] = lo;
    }
    if (idx < 32768) {                   // lstm Wh fragments (pairs)
        int d  = idx >> 6;               // 0..511
        int cp = idx & 63;
        int c  = cp * 2;
        float w0 = Wh[d * HID + c];
        float w1 = Wh[d * HID + c + 1];
        __nv_bfloat16 h0 = __float2bfloat16(w0);
        __nv_bfloat16 h1 = __float2bfloat16(w1);
        __nv_bfloat16 l0 = __float2bfloat16(w0 - __bfloat162float(h0));
        __nv_bfloat16 l1 = __float2bfloat16(w1 - __bfloat162float(h1));
        int w_ = d >> 5, mt = (d >> 4) & 1, r = d & 15;
        int g = r & 7, ir = r >> 3;
        int kt = c >> 4, ck = c & 15;
        int t = (ck & 7) >> 1, ic = (ck >= 8) ? 2 : 0;
        int lane = g * 4 + t;
        int slot = ((((w_ * 2 + mt) * 8 + kt) * 32) + lane) * 4 + (ir + ic);
        g_fAhi[slot] = pkbf(h0, h1);
        g_fAlo[slot] = pkbf(l0, l1);
    }
    if (idx < G4) g_bias[idx] = bi[idx] + bh[idx];
}

// ---------------------------------------------------------------------------
// Conv as mma.sync bf16 GEMM with split-bf16 fp32 emulation (unchanged, passing)
// ---------------------------------------------------------------------------
#define A_PART   25600
#define B_OFF    51200
#define B_BUF    81920
#define B_PART   40960
#define CONV_SMEM (B_OFF + 2 * B_BUF)   // 215040

__device__ __forceinline__ void conv_issue_chunk(char* smem, uint32_t sb, int kc, int tid) {
    const char* src = (const char*)g_Bt + (size_t)kc * 65536;
    uint32_t dstb = sb + B_OFF + (kc & 1) * B_BUF;
    #pragma unroll
    for (int it = 0; it < 16; ++it) {
        int i = tid + it * 256;                 // 0..4095, 16B each
        int p = i >> 11, rem = i & 2047;
        int n = rem >> 2, seg = rem & 3;
        cp_async16(dstb + p * B_PART + n * 80 + seg * 16, src + i * 16);
    }
    CP_COMMIT();
}

__global__ void __launch_bounds__(256, 1)
conv_mma_kernel(const float* __restrict__ x) {
    extern __shared__ char smem[];
    uint32_t sb = smem_u32(smem);
    int tid = threadIdx.x;
    int lane = tid & 31, wid = tid >> 5;
    int t = blockIdx.x;                  // 0..1023  (= hb index)
    int b = t & 15, hr = t >> 4;

    int wm = wid & 1;
    int nbase = (wid >> 1) * 128;

    conv_issue_chunk(smem, sb, 0, tid);

    for (int e = tid; e < 64 * KTOT; e += 256) {
        int m = e & 63, kg = e >> 6;
        int c = kg / 3, kk = kg - 3 * c;
        int wi = m + kk - 1;
        float v = (wi >= 0 && wi < W_) ? x[(((b * C_) + c) * H_ + hr) * W_ + wi] : 0.0f;
        __nv_bfloat16 hi = __float2bfloat16(v);
        __nv_bfloat16 lo = __float2bfloat16(v - __bfloat162float(hi));
        *(__nv_bfloat16*)(smem + 0 * A_PART + m * 400 + kg * 2) = hi;
        *(__nv_bfloat16*)(smem + 1 * A_PART + m * 400 + kg * 2) = lo;
    }

    float d[128];
    #pragma unroll
    for (int i = 0; i < 128; ++i) d[i] = 0.0f;

    int tgrp = lane >> 3, trow = lane & 7;
    uint32_t arow0 = (uint32_t)(wm * 32 + (tgrp & 1) * 8 + trow);
    uint32_t acol16 = (uint32_t)((tgrp >> 1) * 16);
    uint32_t brow = (uint32_t)(nbase + (tgrp >> 1) * 8 + trow);
    uint32_t bk16 = (uint32_t)((tgrp & 1) * 16);

    for (int kc = 0; kc < 6; ++kc) {
        if (kc < 5) {
            conv_issue_chunk(smem, sb, kc + 1, tid);
            asm volatile("cp.async.wait_group 1;" ::: "memory");
        } else {
            asm volatile("cp.async.wait_group 0;" ::: "memory");
        }
        __syncthreads();

        uint32_t Bb = sb + B_OFF + (kc & 1) * B_BUF;

        #pragma unroll
        for (int ks = 0; ks < 2; ++ks) {
            uint32_t kbyteA = (uint32_t)((kc * 32 + ks * 16) * 2) + acol16;
            uint32_t a_hi[2][4], a_lo[2][4];
            #pragma unroll
            for (int ms = 0; ms < 2; ++ms) {
                uint32_t aaddr = sb + (arow0 + ms * 16) * 400 + kbyteA;
                ldmatrix4(a_hi[ms], aaddr);
                ldmatrix4(a_lo[ms], aaddr + A_PART);
            }
            uint32_t bkoff = (uint32_t)(ks * 32) + bk16;

            #pragma unroll
            for (int nbp = 0; nbp < 8; ++nbp) {
                uint32_t bb[4];
                ldmatrix4(bb, Bb + 0 * B_PART + (brow + nbp * 16) * 80 + bkoff);
                #pragma unroll
                for (int ms = 0; ms < 2; ++ms) {
                    mma16816(d + (ms * 16 + 2 * nbp + 0) * 4, a_hi[ms], bb + 0);
                    mma16816(d + (ms * 16 + 2 * nbp + 1) * 4, a_hi[ms], bb + 2);
                    mma16816(d + (ms * 16 + 2 * nbp + 0) * 4, a_lo[ms], bb + 0);
                    mma16816(d + (ms * 16 + 2 * nbp + 1) * 4, a_lo[ms], bb + 2);
                }
            }
            #pragma unroll
            for (int nbp = 0; nbp < 8; ++nbp) {
                uint32_t bb[4];
                ldmatrix4(bb, Bb + 1 * B_PART + (brow + nbp * 16) * 80 + bkoff);
                #pragma unroll
                for (int ms = 0; ms < 2; ++ms) {
                    mma16816(d + (ms * 16 + 2 * nbp + 0) * 4, a_hi[ms], bb + 0);
                    mma16816(d + (ms * 16 + 2 * nbp + 1) * 4, a_hi[ms], bb + 2);
                }
            }
        }
        __syncthreads();
    }

    int qg = lane >> 2, qt = lane & 3;
    #pragma unroll
    for (int ms = 0; ms < 2; ++ms) {
        #pragma unroll
        for (int nb = 0; nb < 16; ++nb) {
            int col = nbase + nb * 8 + qt * 2;
            float2 bv = *(const float2*)(g_bias + col);
            #pragma unroll
            for (int half = 0; half < 2; ++half) {
                int row = t * 64 + wm * 32 + ms * 16 + half * 8 + qg;
                float2 o;
                o.x = d[(ms * 16 + nb) * 4 + half * 2 + 0] + bv.x;
                o.y = d[(ms * 16 + nb) * 4 + half * 2 + 1] + bv.y;
                *(float2*)(g_i2h + (size_t)row * G4 + col) = o;
            }
        }
    }
}

// ---------------------------------------------------------------------------
// Row-LSTM scan via mma.sync. 128 blocks x 512 threads (16 warps).
// Per step: gates(512x8) = i2h + Wh@h as M=512,N=8,K=128 GEMM, 3-pass
// split-bf16 (hh + hl + lh). Wh_hi frags in registers (static), Wh_lo frags
// in smem. h kept as bf16 hi/lo pair-arrays hpk[64][8] (conflict-free b-frags).
// ---------------------------------------------------------------------------
#define LS_ALO_OFF  0                    // 131072 B : Wh_lo fragments
#define LS_HHI_OFF  131072               // 2048 B   : h hi pairs [64][8] u32
#define LS_HLO_OFF  133120               // 2048 B   : h lo pairs
#define LS_GT_OFF   135168               // 16512 B  : gates [8][516] f32
#define LSTM_SMEM   (LS_GT_OFF + 8 * 516 * 4)   // 151680

__global__ void __launch_bounds__(512, 1)
lstm_kernel(float* __restrict__ out) {
    extern __shared__ char smem[];
    uint32_t* alo   = (uint32_t*)(smem + LS_ALO_OFF);
    uint32_t* hhi   = (uint32_t*)(smem + LS_HHI_OFF);
    uint32_t* hlo   = (uint32_t*)(smem + LS_HLO_OFF);
    float*    gt    = (float*)(smem + LS_GT_OFF);

    int blk   = blockIdx.x;
    int b     = blk >> 3;
    int wbase = (blk & 7) * 8;

    int tid  = threadIdx.x;
    int w    = tid >> 5;
    int lane = tid & 31;
    int g    = lane >> 2;          // 0..7 : m-row within tile / n-col for B
    int t    = lane & 3;           // 0..3 : k-pair group / j-col pair

    // ---- load Wh_lo fragments into smem (one-time, 128KB) ----
    {
        const uint4* src = (const uint4*)g_fAlo;
        uint4* dst = (uint4*)alo;
        #pragma unroll
        for (int i = tid; i < 8192; i += 512) dst[i] = src[i];
    }
    // ---- Wh_hi fragments into registers (static across steps) ----
    uint4 ahi[2][8];
    {
        const uint4* src = (const uint4*)g_fAhi;
        #pragma unroll
        for (int mt = 0; mt < 2; ++mt)
            #pragma unroll
            for (int kt = 0; kt < 8; ++kt)
                ahi[mt][kt] = src[(((w * 2 + mt) * 8 + kt) * 32) + lane];
    }

    // zero h pair arrays
    for (int i = tid; i < 512; i += 512) { hhi[i] = 0u; hlo[i] = 0u; }

    // cell-update mapping: thread handles (j0, k0) and (j0, k1)
    int k0 = tid >> 3, j0 = tid & 7;
    int k1 = k0 + 64;
    float cst0 = 0.0f, cst1 = 0.0f;

    // acc/i2h mapping pieces
    int dbase = w * 32;                         // +16*mt, rows g and g+8
    int jj0 = 2 * t, jj1 = 2 * t + 1;           // D cols

    // prefetch i2h for step 0
    float nx[2][4];
    {
        const float* base = g_i2h + ((size_t)((0 * B_ + b) * W_ + wbase)) * G4;
        #pragma unroll
        for (int mt = 0; mt < 2; ++mt) {
            int dd = dbase + 16 * mt + g;
            nx[mt][0] = base[(size_t)jj0 * G4 + dd];
            nx[mt][1] = base[(size_t)jj1 * G4 + dd];
            nx[mt][2] = base[(size_t)jj0 * G4 + dd + 8];
            nx[mt][3] = base[(size_t)jj1 * G4 + dd + 8];
        }
    }

    __syncthreads();

    for (int hr = 0; hr < H_; ++hr) {
        // accumulators start at i2h (bias folded in)
        float acc[2][4];
        #pragma unroll
        for (int mt = 0; mt < 2; ++mt)
            #pragma unroll
            for (int i = 0; i < 4; ++i) acc[mt][i] = nx[mt][i];

        // prefetch next step's i2h (hides HBM latency under the mma work)
        {
            int hn = (hr < H_ - 1) ? hr + 1 : hr;
            const float* base = g_i2h + ((size_t)((hn * B_ + b) * W_ + wbase)) * G4;
            #pragma unroll
            for (int mt = 0; mt < 2; ++mt) {
                int dd = dbase + 16 * mt + g;
                nx[mt][0] = base[(size_t)jj0 * G4 + dd];
                nx[mt][1] = base[(size_t)jj1 * G4 + dd];
                nx[mt][2] = base[(size_t)jj0 * G4 + dd + 8];
                nx[mt][3] = base[(size_t)jj1 * G4 + dd + 8];
            }
        }

        // ---- 3-pass mma GEMM over K=128 (8 ktiles) ----
        #pragma unroll
        for (int kt = 0; kt < 8; ++kt) {
            uint32_t bh[2], bl[2];
            int kp = kt * 8 + t;                 // b0 pair index
            bh[0] = hhi[kp * 8 + g];
            bh[1] = hhi[(kp + 4) * 8 + g];
            bl[0] = hlo[kp * 8 + g];
            bl[1] = hlo[(kp + 4) * 8 + g];

            // hh + hl (A_hi from registers)
            mma16816(acc[0], (const uint32_t*)&ahi[0][kt], bh);
            mma16816(acc[1], (const uint32_t*)&ahi[1][kt], bh);
            mma16816(acc[0], (const uint32_t*)&ahi[0][kt], bl);
            mma16816(acc[1], (const uint32_t*)&ahi[1][kt], bl);

            // lh (A_lo from smem)
            uint32_t al0[4], al1[4];
            *(uint4*)al0 = *(const uint4*)&alo[(((w * 2 + 0) * 8 + kt) * 32 + lane) * 4];
            *(uint4*)al1 = *(const uint4*)&alo[(((w * 2 + 1) * 8 + kt) * 32 + lane) * 4];
            mma16816(acc[0], al0, bh);
            mma16816(acc[1], al1, bh);
        }

        // ---- write gates to smem: gt[j*516 + d] ----
        #pragma unroll
        for (int mt = 0; mt < 2; ++mt) {
            int dd = dbase + 16 * mt + g;
            gt[jj0 * 516 + dd]     = acc[mt][0];
            gt[jj1 * 516 + dd]     = acc[mt][1];
            gt[jj0 * 516 + dd + 8] = acc[mt][2];
            gt[jj1 * 516 + dd + 8] = acc[mt][3];
        }
        __syncthreads();

        // ---- cell update: 2 (col,k) pairs per thread ----
        {
            float ig = gt[j0 * 516 + k0];
            float fg = gt[j0 * 516 + k0 + 128];
            float og = gt[j0 * 516 + k0 + 256];
            float gg = gt[j0 * 516 + k0 + 384];
            cst0 = siga(fg) * cst0 + siga(ig) * tanhe(gg);
            float hv = siga(og) * tanhe(cst0);
            __nv_bfloat16 hh = __float2bfloat16(hv);
            __nv_bfloat16 hl = __float2bfloat16(hv - __bfloat162float(hh));
            ((__nv_bfloat16*)hhi)[((k0 >> 1) * 8 + j0) * 2 + (k0 & 1)] = hh;
            ((__nv_bfloat16*)hlo)[((k0 >> 1) * 8 + j0) * 2 + (k0 & 1)] = hl;
            out[(((b * HID) + k0) * H_ + hr) * W_ + (wbase + j0)] = hv;
        }
        {
            float ig = gt[j0 * 516 + k1];
            float fg = gt[j0 * 516 + k1 + 128];
            float og = gt[j0 * 516 + k1 + 256];
            float gg = gt[j0 * 516 + k1 + 384];
            cst1 = siga(fg) * cst1 + siga(ig) * tanhe(gg);
            float hv = siga(og) * tanhe(cst1);
            __nv_bfloat16 hh = __float2bfloat16(hv);
            __nv_bfloat16 hl = __float2bfloat16(hv - __bfloat162float(hh));
            ((__nv_bfloat16*)hhi)[((k1 >> 1) * 8 + j0) * 2 + (k1 & 1)] = hh;
            ((__nv_bfloat16*)hlo)[((k1 >> 1) * 8 + j0) * 2 + (k1 & 1)] = hl;
            out[(((b * HID) + k1) * H_ + hr) * W_ + (wbase + j0)] = hv;
        }
        __syncthreads();
    }
}

// ---------------------------------------------------------------------------
extern "C" void kernel_launch(void* const* d_in, const int* in_sizes, int n_in,
                              void* d_out, int out_size) {
    const float* x  = (const float*)d_in[0];
    const float* Wi = (const float*)d_in[1];
    const float* bi = (const float*)d_in[2];
    const float* Wh = (const float*)d_in[3];
    const float* bh = (const float*)d_in[4];
    float* out = (float*)d_out;

    static bool attr_set = false;
    if (!attr_set) {
        cudaFuncSetAttribute(conv_mma_kernel, cudaFuncAttributeMaxDynamicSharedMemorySize, CONV_SMEM);
        cudaFuncSetAttribute(lstm_kernel, cudaFuncAttributeMaxDynamicSharedMemorySize, LSTM_SMEM);
        attr_set = true;
    }

    prep_kernel<<<384, 256>>>(Wi, Wh, bi, bh);
    conv_mma_kernel<<<1024, 256, CONV_SMEM>>>(x);
    lstm_kernel<<<128, 512, LSTM_SMEM>>>(out);
}

// round 13
// speedup vs baseline: 2.8474x; 1.1268x over previous
#include <cuda_runtime.h>
#include <cuda_bf16.h>
#include <cuda_fp16.h>
#include <cstdint>

// Problem constants
#define B_   16
#define C_   64
#define H_   64
#define W_   64
#define HID  128
#define G4   512          // 4*HID
#define KTOT 192          // C_*3

// ---------------------------------------------------------------------------
// Scratch (device globals — no allocation allowed)
// ---------------------------------------------------------------------------
__device__ float g_i2h[H_ * B_ * W_ * G4];          // (h, b, w, d) : 134 MB
__device__ float g_bias[G4];                        // bi + bh (folded)
// conv B pack: [kc][part][d][kk]  (6 x 2 x 512 x 32 bf16) = 384KB
__device__ __nv_bfloat16 g_Bt[6 * 2 * G4 * 32];
// lstm Wh mma fragments (fp16 pairs), PTX m16n8k16 A-fragment order:
// slot = ((((warp*2+mt)*8 + kt)*32) + lane)*4 + i
__device__ uint32_t g_fA[32768];                    // 128KB

typedef unsigned long long ull;

__device__ __forceinline__ uint32_t smem_u32(const void* p) {
    uint32_t a;
    asm("{ .reg .u64 t; cvta.to.shared.u64 t, %1; cvt.u32.u64 %0, t; }" : "=r"(a) : "l"(p));
    return a;
}

// fast exact-ish sigmoid / tanh (MUFU ex2 + rcp, ~2^-20 rel err)
__device__ __forceinline__ float siga(float x) {
    float t;
    asm("ex2.approx.f32 %0, %1;" : "=f"(t) : "f"(-1.4426950408889634f * x));
    float r;
    asm("rcp.approx.f32 %0, %1;" : "=f"(r) : "f"(1.0f + t));
    return r;
}
__device__ __forceinline__ float tanhe(float x) { return 2.0f * siga(2.0f * x) - 1.0f; }

// ---- baseline-PTX building blocks (sm_80-era: OK on plain compute_103) ----
__device__ __forceinline__ void ldmatrix4(uint32_t* r, uint32_t addr) {
    asm volatile("ldmatrix.sync.aligned.m8n8.x4.shared.b16 {%0,%1,%2,%3}, [%4];"
                 : "=r"(r[0]), "=r"(r[1]), "=r"(r[2]), "=r"(r[3]) : "r"(addr));
}
__device__ __forceinline__ void mma16816(float* d, const uint32_t* a, const uint32_t* b) {
    asm volatile("mma.sync.aligned.m16n8k16.row.col.f32.bf16.bf16.f32 "
                 "{%0,%1,%2,%3}, {%4,%5,%6,%7}, {%8,%9}, {%0,%1,%2,%3};"
                 : "+f"(d[0]), "+f"(d[1]), "+f"(d[2]), "+f"(d[3])
                 : "r"(a[0]), "r"(a[1]), "r"(a[2]), "r"(a[3]), "r"(b[0]), "r"(b[1]));
}
__device__ __forceinline__ void mma16816h(float* d, const uint32_t* a, const uint32_t* b) {
    asm volatile("mma.sync.aligned.m16n8k16.row.col.f32.f16.f16.f32 "
                 "{%0,%1,%2,%3}, {%4,%5,%6,%7}, {%8,%9}, {%0,%1,%2,%3};"
                 : "+f"(d[0]), "+f"(d[1]), "+f"(d[2]), "+f"(d[3])
                 : "r"(a[0]), "r"(a[1]), "r"(a[2]), "r"(a[3]), "r"(b[0]), "r"(b[1]));
}
__device__ __forceinline__ void cp_async16(uint32_t dst, const void* src) {
    asm volatile("cp.async.cg.shared.global [%0], [%1], 16;" :: "r"(dst), "l"(src));
}
#define CP_COMMIT() asm volatile("cp.async.commit_group;" ::: "memory")

__device__ __forceinline__ uint32_t pkh(__half lo, __half hi) {
    return (uint32_t)__half_as_ushort(lo) | ((uint32_t)__half_as_ushort(hi) << 16);
}

// ---------------------------------------------------------------------------
// Prep: conv Wi hi/lo bf16 pack, lstm Wh fp16 fragments, fused bias.
// ---------------------------------------------------------------------------
__global__ void prep_kernel(const float* __restrict__ Wi,
                            const float* __restrict__ Wh,
                            const float* __restrict__ bi,
                            const float* __restrict__ bh) {
    int idx = blockIdx.x * blockDim.x + threadIdx.x;
    if (idx < G4 * KTOT) {               // 98304 : conv B tiles
        int d = idx / KTOT;
        int k = idx % KTOT;
        int kc = k >> 5, kk = k & 31;
        float v = Wi[idx];
        __nv_bfloat16 hi = __float2bfloat16(v);
        __nv_bfloat16 lo = __float2bfloat16(v - __bfloat162float(hi));
        g_Bt[((kc * 2 + 0) * G4 + d) * 32 + kk] = hi;
        g_Bt[((kc * 2 + 1) * G4 + d) * 32 + kk] = lo;
    }
    if (idx < 32768) {                   // lstm Wh fp16 fragments (pairs)
        int d  = idx >> 6;               // 0..511
        int cp = idx & 63;
        int c  = cp * 2;
        __half h0 = __float2half(Wh[d * HID + c]);
        __half h1 = __float2half(Wh[d * HID + c + 1]);
        int w_ = d >> 5, mt = (d >> 4) & 1, r = d & 15;
        int g = r & 7, ir = r >> 3;
        int kt = c >> 4, ck = c & 15;
        int t = (ck & 7) >> 1, ic = (ck >= 8) ? 2 : 0;
        int lane = g * 4 + t;
        int slot = ((((w_ * 2 + mt) * 8 + kt) * 32) + lane) * 4 + (ir + ic);
        g_fA[slot] = pkh(h0, h1);
    }
    if (idx < G4) g_bias[idx] = bi[idx] + bh[idx];
}

// ---------------------------------------------------------------------------
// Conv as mma.sync bf16 GEMM with split-bf16 fp32 emulation (unchanged, passing)
// ---------------------------------------------------------------------------
#define A_PART   25600
#define B_OFF    51200
#define B_BUF    81920
#define B_PART   40960
#define CONV_SMEM (B_OFF + 2 * B_BUF)   // 215040

__device__ __forceinline__ void conv_issue_chunk(char* smem, uint32_t sb, int kc, int tid) {
    const char* src = (const char*)g_Bt + (size_t)kc * 65536;
    uint32_t dstb = sb + B_OFF + (kc & 1) * B_BUF;
    #pragma unroll
    for (int it = 0; it < 16; ++it) {
        int i = tid + it * 256;                 // 0..4095, 16B each
        int p = i >> 11, rem = i & 2047;
        int n = rem >> 2, seg = rem & 3;
        cp_async16(dstb + p * B_PART + n * 80 + seg * 16, src + i * 16);
    }
    CP_COMMIT();
}

__global__ void __launch_bounds__(256, 1)
conv_mma_kernel(const float* __restrict__ x) {
    extern __shared__ char smem[];
    uint32_t sb = smem_u32(smem);
    int tid = threadIdx.x;
    int lane = tid & 31, wid = tid >> 5;
    int t = blockIdx.x;                  // 0..1023  (= hb index)
    int b = t & 15, hr = t >> 4;

    int wm = wid & 1;
    int nbase = (wid >> 1) * 128;

    conv_issue_chunk(smem, sb, 0, tid);

    for (int e = tid; e < 64 * KTOT; e += 256) {
        int m = e & 63, kg = e >> 6;
        int c = kg / 3, kk = kg - 3 * c;
        int wi = m + kk - 1;
        float v = (wi >= 0 && wi < W_) ? x[(((b * C_) + c) * H_ + hr) * W_ + wi] : 0.0f;
        __nv_bfloat16 hi = __float2bfloat16(v);
        __nv_bfloat16 lo = __float2bfloat16(v - __bfloat162float(hi));
        *(__nv_bfloat16*)(smem + 0 * A_PART + m * 400 + kg * 2) = hi;
        *(__nv_bfloat16*)(smem + 1 * A_PART + m * 400 + kg * 2) = lo;
    }

    float d[128];
    #pragma unroll
    for (int i = 0; i < 128; ++i) d[i] = 0.0f;

    int tgrp = lane >> 3, trow = lane & 7;
    uint32_t arow0 = (uint32_t)(wm * 32 + (tgrp & 1) * 8 + trow);
    uint32_t acol16 = (uint32_t)((tgrp >> 1) * 16);
    uint32_t brow = (uint32_t)(nbase + (tgrp >> 1) * 8 + trow);
    uint32_t bk16 = (uint32_t)((tgrp & 1) * 16);

    for (int kc = 0; kc < 6; ++kc) {
        if (kc < 5) {
            conv_issue_chunk(smem, sb, kc + 1, tid);
            asm volatile("cp.async.wait_group 1;" ::: "memory");
        } else {
            asm volatile("cp.async.wait_group 0;" ::: "memory");
        }
        __syncthreads();

        uint32_t Bb = sb + B_OFF + (kc & 1) * B_BUF;

        #pragma unroll
        for (int ks = 0; ks < 2; ++ks) {
            uint32_t kbyteA = (uint32_t)((kc * 32 + ks * 16) * 2) + acol16;
            uint32_t a_hi[2][4], a_lo[2][4];
            #pragma unroll
            for (int ms = 0; ms < 2; ++ms) {
                uint32_t aaddr = sb + (arow0 + ms * 16) * 400 + kbyteA;
                ldmatrix4(a_hi[ms], aaddr);
                ldmatrix4(a_lo[ms], aaddr + A_PART);
            }
            uint32_t bkoff = (uint32_t)(ks * 32) + bk16;

            #pragma unroll
            for (int nbp = 0; nbp < 8; ++nbp) {
                uint32_t bb[4];
                ldmatrix4(bb, Bb + 0 * B_PART + (brow + nbp * 16) * 80 + bkoff);
                #pragma unroll
                for (int ms = 0; ms < 2; ++ms) {
                    mma16816(d + (ms * 16 + 2 * nbp + 0) * 4, a_hi[ms], bb + 0);
                    mma16816(d + (ms * 16 + 2 * nbp + 1) * 4, a_hi[ms], bb + 2);
                    mma16816(d + (ms * 16 + 2 * nbp + 0) * 4, a_lo[ms], bb + 0);
                    mma16816(d + (ms * 16 + 2 * nbp + 1) * 4, a_lo[ms], bb + 2);
                }
            }
            #pragma unroll
            for (int nbp = 0; nbp < 8; ++nbp) {
                uint32_t bb[4];
                ldmatrix4(bb, Bb + 1 * B_PART + (brow + nbp * 16) * 80 + bkoff);
                #pragma unroll
                for (int ms = 0; ms < 2; ++ms) {
                    mma16816(d + (ms * 16 + 2 * nbp + 0) * 4, a_hi[ms], bb + 0);
                    mma16816(d + (ms * 16 + 2 * nbp + 1) * 4, a_hi[ms], bb + 2);
                }
            }
        }
        __syncthreads();
    }

    int qg = lane >> 2, qt = lane & 3;
    #pragma unroll
    for (int ms = 0; ms < 2; ++ms) {
        #pragma unroll
        for (int nb = 0; nb < 16; ++nb) {
            int col = nbase + nb * 8 + qt * 2;
            float2 bv = *(const float2*)(g_bias + col);
            #pragma unroll
            for (int half = 0; half < 2; ++half) {
                int row = t * 64 + wm * 32 + ms * 16 + half * 8 + qg;
                float2 o;
                o.x = d[(ms * 16 + nb) * 4 + half * 2 + 0] + bv.x;
                o.y = d[(ms * 16 + nb) * 4 + half * 2 + 1] + bv.y;
                *(float2*)(g_i2h + (size_t)row * G4 + col) = o;
            }
        }
    }
}

// ---------------------------------------------------------------------------
// Row-LSTM scan via single-pass fp16 mma.sync. 128 blocks x 512 threads.
// Per step: gates(512x8) = i2h + Wh@h, M=512/N=8/K=128, ONE fp16 pass
// (error decays through the forget gate; see round analysis).
// Wh fp16 fragments fully register-resident; h as fp16 pairs in smem.
// ---------------------------------------------------------------------------
#define LS_HP_OFF   0                    // 2048 B : h pairs [64][8] u32 (fp16x2)
#define LS_GT_OFF   2048                 // gates [8][516] f32
#define LSTM_SMEM   (LS_GT_OFF + 8 * 516 * 4)   // 18560

__global__ void __launch_bounds__(512, 1)
lstm_kernel(float* __restrict__ out) {
    extern __shared__ char smem[];
    uint32_t* hp = (uint32_t*)(smem + LS_HP_OFF);
    float*    gt = (float*)(smem + LS_GT_OFF);

    int blk   = blockIdx.x;
    int b     = blk >> 3;
    int wbase = (blk & 7) * 8;

    int tid  = threadIdx.x;
    int w    = tid >> 5;
    int lane = tid & 31;
    int g    = lane >> 2;          // 0..7
    int t    = lane & 3;           // 0..3

    // ---- Wh fp16 fragments into registers (static across steps) ----
    uint4 ah[2][8];
    {
        const uint4* src = (const uint4*)g_fA;
        #pragma unroll
        for (int mt = 0; mt < 2; ++mt)
            #pragma unroll
            for (int kt = 0; kt < 8; ++kt)
                ah[mt][kt] = src[(((w * 2 + mt) * 8 + kt) * 32) + lane];
    }

    // zero h pairs
    for (int i = tid; i < 512; i += 512) hp[i] = 0u;

    // cell-update mapping: thread handles (j0, k0) and (j0, k1)
    int k0 = tid >> 3, j0 = tid & 7;
    int k1 = k0 + 64;
    float cst0 = 0.0f, cst1 = 0.0f;

    // acc/i2h mapping pieces
    int dbase = w * 32;
    int jj0 = 2 * t, jj1 = 2 * t + 1;

    // prefetch i2h for step 0
    float nx[2][4];
    {
        const float* base = g_i2h + ((size_t)((0 * B_ + b) * W_ + wbase)) * G4;
        #pragma unroll
        for (int mt = 0; mt < 2; ++mt) {
            int dd = dbase + 16 * mt + g;
            nx[mt][0] = base[(size_t)jj0 * G4 + dd];
            nx[mt][1] = base[(size_t)jj1 * G4 + dd];
            nx[mt][2] = base[(size_t)jj0 * G4 + dd + 8];
            nx[mt][3] = base[(size_t)jj1 * G4 + dd + 8];
        }
    }

    __syncthreads();

    for (int hr = 0; hr < H_; ++hr) {
        // accumulators start at i2h (bias folded in)
        float acc[2][4];
        #pragma unroll
        for (int mt = 0; mt < 2; ++mt)
            #pragma unroll
            for (int i = 0; i < 4; ++i) acc[mt][i] = nx[mt][i];

        // prefetch next step's i2h (hides HBM latency under the mma work)
        {
            int hn = (hr < H_ - 1) ? hr + 1 : hr;
            const float* base = g_i2h + ((size_t)((hn * B_ + b) * W_ + wbase)) * G4;
            #pragma unroll
            for (int mt = 0; mt < 2; ++mt) {
                int dd = dbase + 16 * mt + g;
                nx[mt][0] = base[(size_t)jj0 * G4 + dd];
                nx[mt][1] = base[(size_t)jj1 * G4 + dd];
                nx[mt][2] = base[(size_t)jj0 * G4 + dd + 8];
                nx[mt][3] = base[(size_t)jj1 * G4 + dd + 8];
            }
        }

        // ---- single-pass fp16 mma GEMM over K=128 (8 ktiles) ----
        #pragma unroll
        for (int kt = 0; kt < 8; ++kt) {
            uint32_t bh[2];
            int kp = kt * 8 + t;
            bh[0] = hp[kp * 8 + g];
            bh[1] = hp[(kp + 4) * 8 + g];
            mma16816h(acc[0], (const uint32_t*)&ah[0][kt], bh);
            mma16816h(acc[1], (const uint32_t*)&ah[1][kt], bh);
        }

        // ---- write gates to smem: gt[j*516 + d] ----
        #pragma unroll
        for (int mt = 0; mt < 2; ++mt) {
            int dd = dbase + 16 * mt + g;
            gt[jj0 * 516 + dd]     = acc[mt][0];
            gt[jj1 * 516 + dd]     = acc[mt][1];
            gt[jj0 * 516 + dd + 8] = acc[mt][2];
            gt[jj1 * 516 + dd + 8] = acc[mt][3];
        }
        __syncthreads();

        // ---- cell update: 2 (col,k) pairs per thread ----
        {
            float ig = gt[j0 * 516 + k0];
            float fg = gt[j0 * 516 + k0 + 128];
            float og = gt[j0 * 516 + k0 + 256];
            float gg = gt[j0 * 516 + k0 + 384];
            cst0 = siga(fg) * cst0 + siga(ig) * tanhe(gg);
            float hv = siga(og) * tanhe(cst0);
            ((__half*)hp)[((k0 >> 1) * 8 + j0) * 2 + (k0 & 1)] = __float2half(hv);
            out[(((b * HID) + k0) * H_ + hr) * W_ + (wbase + j0)] = hv;
        }
        {
            float ig = gt[j0 * 516 + k1];
            float fg = gt[j0 * 516 + k1 + 128];
            float og = gt[j0 * 516 + k1 + 256];
            float gg = gt[j0 * 516 + k1 + 384];
            cst1 = siga(fg) * cst1 + siga(ig) * tanhe(gg);
            float hv = siga(og) * tanhe(cst1);
            ((__half*)hp)[((k1 >> 1) * 8 + j0) * 2 + (k1 & 1)] = __float2half(hv);
            out[(((b * HID) + k1) * H_ + hr) * W_ + (wbase + j0)] = hv;
        }
        __syncthreads();
    }
}

// ---------------------------------------------------------------------------
extern "C" void kernel_launch(void* const* d_in, const int* in_sizes, int n_in,
                              void* d_out, int out_size) {
    const float* x  = (const float*)d_in[0];
    const float* Wi = (const float*)d_in[1];
    const float* bi = (const float*)d_in[2];
    const float* Wh = (const float*)d_in[3];
    const float* bh = (const float*)d_in[4];
    float* out = (float*)d_out;

    static bool attr_set = false;
    if (!attr_set) {
        cudaFuncSetAttribute(conv_mma_kernel, cudaFuncAttributeMaxDynamicSharedMemorySize, CONV_SMEM);
        cudaFuncSetAttribute(lstm_kernel, cudaFuncAttributeMaxDynamicSharedMemorySize, LSTM_SMEM);
        attr_set = true;
    }

    prep_kernel<<<384, 256>>>(Wi, Wh, bi, bh);
    conv_mma_kernel<<<1024, 256, CONV_SMEM>>>(x);
    lstm_kernel<<<128, 512, LSTM_SMEM>>>(out);
}

// round 16
// speedup vs baseline: 2.8787x; 1.0110x over previous
#include <cuda_runtime.h>
#include <cuda_bf16.h>
#include <cuda_fp16.h>
#include <cstdint>

// Problem constants
#define B_   16
#define C_   64
#define H_   64
#define W_   64
#define HID  128
#define G4   512          // 4*HID
#define KTOT 192          // C_*3

// ---------------------------------------------------------------------------
// Scratch (device globals — no allocation allowed)
// ---------------------------------------------------------------------------
__device__ float g_i2h[H_ * B_ * W_ * G4];          // (h, b, w, d) : 134 MB
__device__ float g_bias[G4];                        // bi + bh (folded)
// conv B pack: [kc][part][d][kk]  (6 x 2 x 512 x 32 bf16) = 384KB
__device__ __nv_bfloat16 g_Bt[6 * 2 * G4 * 32];
// lstm Wh mma fragments (fp16 pairs), PTX m16n8k16 A-fragment order:
// slot = ((((warp*2+mt)*8 + kt)*32) + lane)*4 + i
__device__ uint32_t g_fA[32768];                    // 128KB

typedef unsigned long long ull;

__device__ __forceinline__ uint32_t smem_u32(const void* p) {
    uint32_t a;
    asm("{ .reg .u64 t; cvta.to.shared.u64 t, %1; cvt.u32.u64 %0, t; }" : "=r"(a) : "l"(p));
    return a;
}

// fast exact-ish sigmoid / tanh (MUFU ex2 + rcp, ~2^-20 rel err)
__device__ __forceinline__ float siga(float x) {
    float t;
    asm("ex2.approx.f32 %0, %1;" : "=f"(t) : "f"(-1.4426950408889634f * x));
    float r;
    asm("rcp.approx.f32 %0, %1;" : "=f"(r) : "f"(1.0f + t));
    return r;
}
__device__ __forceinline__ float tanhe(float x) { return 2.0f * siga(2.0f * x) - 1.0f; }

// ---- baseline-PTX building blocks (sm_80-era: OK on plain compute_103) ----
__device__ __forceinline__ void ldmatrix4(uint32_t* r, uint32_t addr) {
    asm volatile("ldmatrix.sync.aligned.m8n8.x4.shared.b16 {%0,%1,%2,%3}, [%4];"
                 : "=r"(r[0]), "=r"(r[1]), "=r"(r[2]), "=r"(r[3]) : "r"(addr));
}
__device__ __forceinline__ void mma16816(float* d, const uint32_t* a, const uint32_t* b) {
    asm volatile("mma.sync.aligned.m16n8k16.row.col.f32.bf16.bf16.f32 "
                 "{%0,%1,%2,%3}, {%4,%5,%6,%7}, {%8,%9}, {%0,%1,%2,%3};"
                 : "+f"(d[0]), "+f"(d[1]), "+f"(d[2]), "+f"(d[3])
                 : "r"(a[0]), "r"(a[1]), "r"(a[2]), "r"(a[3]), "r"(b[0]), "r"(b[1]));
}
__device__ __forceinline__ void mma16816h(float* d, const uint32_t* a, const uint32_t* b) {
    asm volatile("mma.sync.aligned.m16n8k16.row.col.f32.f16.f16.f32 "
                 "{%0,%1,%2,%3}, {%4,%5,%6,%7}, {%8,%9}, {%0,%1,%2,%3};"
                 : "+f"(d[0]), "+f"(d[1]), "+f"(d[2]), "+f"(d[3])
                 : "r"(a[0]), "r"(a[1]), "r"(a[2]), "r"(a[3]), "r"(b[0]), "r"(b[1]));
}
__device__ __forceinline__ void cp_async16(uint32_t dst, const void* src) {
    asm volatile("cp.async.cg.shared.global [%0], [%1], 16;" :: "r"(dst), "l"(src));
}
#define CP_COMMIT() asm volatile("cp.async.commit_group;" ::: "memory")

__device__ __forceinline__ uint32_t pkh(__half lo, __half hi) {
    return (uint32_t)__half_as_ushort(lo) | ((uint32_t)__half_as_ushort(hi) << 16);
}

// ---------------------------------------------------------------------------
// Prep: conv Wi hi/lo bf16 pack, lstm Wh fp16 fragments, fused bias.
// ---------------------------------------------------------------------------
__global__ void prep_kernel(const float* __restrict__ Wi,
                            const float* __restrict__ Wh,
                            const float* __restrict__ bi,
                            const float* __restrict__ bh) {
    int idx = blockIdx.x * blockDim.x + threadIdx.x;
    if (idx < G4 * KTOT) {               // 98304 : conv B tiles
        int d = idx / KTOT;
        int k = idx % KTOT;
        int kc = k >> 5, kk = k & 31;
        float v = Wi[idx];
        __nv_bfloat16 hi = __float2bfloat16(v);
        __nv_bfloat16 lo = __float2bfloat16(v - __bfloat162float(hi));
        g_Bt[((kc * 2 + 0) * G4 + d) * 32 + kk] = hi;
        g_Bt[((kc * 2 + 1) * G4 + d) * 32 + kk] = lo;
    }
    if (idx < 32768) {                   // lstm Wh fp16 fragments (pairs)
        int d  = idx >> 6;               // 0..511
        int cp = idx & 63;
        int c  = cp * 2;
        __half h0 = __float2half(Wh[d * HID + c]);
        __half h1 = __float2half(Wh[d * HID + c + 1]);
        int w_ = d >> 5, mt = (d >> 4) & 1, r = d & 15;
        int g = r & 7, ir = r >> 3;
        int kt = c >> 4, ck = c & 15;
        int t = (ck & 7) >> 1, ic = (ck >= 8) ? 2 : 0;
        int lane = g * 4 + t;
        int slot = ((((w_ * 2 + mt) * 8 + kt) * 32) + lane) * 4 + (ir + ic);
        g_fA[slot] = pkh(h0, h1);
    }
    if (idx < G4) g_bias[idx] = bi[idx] + bh[idx];
}

// ---------------------------------------------------------------------------
// Conv as mma.sync bf16 GEMM with split-bf16 fp32 emulation (unchanged, passing)
// ---------------------------------------------------------------------------
#define A_PART   25600
#define B_OFF    51200
#define B_BUF    81920
#define B_PART   40960
#define CONV_SMEM (B_OFF + 2 * B_BUF)   // 215040

__device__ __forceinline__ void conv_issue_chunk(char* smem, uint32_t sb, int kc, int tid) {
    const char* src = (const char*)g_Bt + (size_t)kc * 65536;
    uint32_t dstb = sb + B_OFF + (kc & 1) * B_BUF;
    #pragma unroll
    for (int it = 0; it < 16; ++it) {
        int i = tid + it * 256;                 // 0..4095, 16B each
        int p = i >> 11, rem = i & 2047;
        int n = rem >> 2, seg = rem & 3;
        cp_async16(dstb + p * B_PART + n * 80 + seg * 16, src + i * 16);
    }
    CP_COMMIT();
}

__global__ void __launch_bounds__(256, 1)
conv_mma_kernel(const float* __restrict__ x) {
    extern __shared__ char smem[];
    uint32_t sb = smem_u32(smem);
    int tid = threadIdx.x;
    int lane = tid & 31, wid = tid >> 5;
    int t = blockIdx.x;                  // 0..1023  (= hb index)
    int b = t & 15, hr = t >> 4;

    int wm = wid & 1;
    int nbase = (wid >> 1) * 128;

    conv_issue_chunk(smem, sb, 0, tid);

    for (int e = tid; e < 64 * KTOT; e += 256) {
        int m = e & 63, kg = e >> 6;
        int c = kg / 3, kk = kg - 3 * c;
        int wi = m + kk - 1;
        float v = (wi >= 0 && wi < W_) ? x[(((b * C_) + c) * H_ + hr) * W_ + wi] : 0.0f;
        __nv_bfloat16 hi = __float2bfloat16(v);
        __nv_bfloat16 lo = __float2bfloat16(v - __bfloat162float(hi));
        *(__nv_bfloat16*)(smem + 0 * A_PART + m * 400 + kg * 2) = hi;
        *(__nv_bfloat16*)(smem + 1 * A_PART + m * 400 + kg * 2) = lo;
    }

    float d[128];
    #pragma unroll
    for (int i = 0; i < 128; ++i) d[i] = 0.0f;

    int tgrp = lane >> 3, trow = lane & 7;
    uint32_t arow0 = (uint32_t)(wm * 32 + (tgrp & 1) * 8 + trow);
    uint32_t acol16 = (uint32_t)((tgrp >> 1) * 16);
    uint32_t brow = (uint32_t)(nbase + (tgrp >> 1) * 8 + trow);
    uint32_t bk16 = (uint32_t)((tgrp & 1) * 16);

    for (int kc = 0; kc < 6; ++kc) {
        if (kc < 5) {
            conv_issue_chunk(smem, sb, kc + 1, tid);
            asm volatile("cp.async.wait_group 1;" ::: "memory");
        } else {
            asm volatile("cp.async.wait_group 0;" ::: "memory");
        }
        __syncthreads();

        uint32_t Bb = sb + B_OFF + (kc & 1) * B_BUF;

        #pragma unroll
        for (int ks = 0; ks < 2; ++ks) {
            uint32_t kbyteA = (uint32_t)((kc * 32 + ks * 16) * 2) + acol16;
            uint32_t a_hi[2][4], a_lo[2][4];
            #pragma unroll
            for (int ms = 0; ms < 2; ++ms) {
                uint32_t aaddr = sb + (arow0 + ms * 16) * 400 + kbyteA;
                ldmatrix4(a_hi[ms], aaddr);
                ldmatrix4(a_lo[ms], aaddr + A_PART);
            }
            uint32_t bkoff = (uint32_t)(ks * 32) + bk16;

            #pragma unroll
            for (int nbp = 0; nbp < 8; ++nbp) {
                uint32_t bb[4];
                ldmatrix4(bb, Bb + 0 * B_PART + (brow + nbp * 16) * 80 + bkoff);
                #pragma unroll
                for (int ms = 0; ms < 2; ++ms) {
                    mma16816(d + (ms * 16 + 2 * nbp + 0) * 4, a_hi[ms], bb + 0);
                    mma16816(d + (ms * 16 + 2 * nbp + 1) * 4, a_hi[ms], bb + 2);
                    mma16816(d + (ms * 16 + 2 * nbp + 0) * 4, a_lo[ms], bb + 0);
                    mma16816(d + (ms * 16 + 2 * nbp + 1) * 4, a_lo[ms], bb + 2);
                }
            }
            #pragma unroll
            for (int nbp = 0; nbp < 8; ++nbp) {
                uint32_t bb[4];
                ldmatrix4(bb, Bb + 1 * B_PART + (brow + nbp * 16) * 80 + bkoff);
                #pragma unroll
                for (int ms = 0; ms < 2; ++ms) {
                    mma16816(d + (ms * 16 + 2 * nbp + 0) * 4, a_hi[ms], bb + 0);
                    mma16816(d + (ms * 16 + 2 * nbp + 1) * 4, a_hi[ms], bb + 2);
                }
            }
        }
        __syncthreads();
    }

    int qg = lane >> 2, qt = lane & 3;
    #pragma unroll
    for (int ms = 0; ms < 2; ++ms) {
        #pragma unroll
        for (int nb = 0; nb < 16; ++nb) {
            int col = nbase + nb * 8 + qt * 2;
            float2 bv = *(const float2*)(g_bias + col);
            #pragma unroll
            for (int half = 0; half < 2; ++half) {
                int row = t * 64 + wm * 32 + ms * 16 + half * 8 + qg;
                float2 o;
                o.x = d[(ms * 16 + nb) * 4 + half * 2 + 0] + bv.x;
                o.y = d[(ms * 16 + nb) * 4 + half * 2 + 1] + bv.y;
                *(float2*)(g_i2h + (size_t)row * G4 + col) = o;
            }
        }
    }
}

// ---------------------------------------------------------------------------
// Row-LSTM scan via single-pass fp16 mma.sync. 128 blocks x 512 threads.
// Per step: gates(512x8) = i2h + Wh@h, M=512/N=8/K=128, ONE fp16 pass
// (error decays through the forget gate; see round analysis).
// Wh fp16 fragments fully register-resident; h as fp16 pairs in smem.
// ---------------------------------------------------------------------------
#define LS_HP_OFF   0                    // 2048 B : h pairs [64][8] u32 (fp16x2)
#define LS_GT_OFF   2048                 // gates [8][516] f32
#define LSTM_SMEM   (LS_GT_OFF + 8 * 516 * 4)   // 18560

__global__ void __launch_bounds__(512, 1)
lstm_kernel(float* __restrict__ out) {
    extern __shared__ char smem[];
    uint32_t* hp = (uint32_t*)(smem + LS_HP_OFF);
    float*    gt = (float*)(smem + LS_GT_OFF);

    int blk   = blockIdx.x;
    int b     = blk >> 3;
    int wbase = (blk & 7) * 8;

    int tid  = threadIdx.x;
    int w    = tid >> 5;
    int lane = tid & 31;
    int g    = lane >> 2;          // 0..7
    int t    = lane & 3;           // 0..3

    // ---- Wh fp16 fragments into registers (static across steps) ----
    uint4 ah[2][8];
    {
        const uint4* src = (const uint4*)g_fA;
        #pragma unroll
        for (int mt = 0; mt < 2; ++mt)
            #pragma unroll
            for (int kt = 0; kt < 8; ++kt)
                ah[mt][kt] = src[(((w * 2 + mt) * 8 + kt) * 32) + lane];
    }

    // zero h pairs
    for (int i = tid; i < 512; i += 512) hp[i] = 0u;

    // cell-update mapping: thread handles (j0, k0) and (j0, k1)
    int k0 = tid >> 3, j0 = tid & 7;
    int k1 = k0 + 64;
    float cst0 = 0.0f, cst1 = 0.0f;

    // acc/i2h mapping pieces
    int dbase = w * 32;
    int jj0 = 2 * t, jj1 = 2 * t + 1;

    // prefetch i2h for step 0
    float nx[2][4];
    {
        const float* base = g_i2h + ((size_t)((0 * B_ + b) * W_ + wbase)) * G4;
        #pragma unroll
        for (int mt = 0; mt < 2; ++mt) {
            int dd = dbase + 16 * mt + g;
            nx[mt][0] = base[(size_t)jj0 * G4 + dd];
            nx[mt][1] = base[(size_t)jj1 * G4 + dd];
            nx[mt][2] = base[(size_t)jj0 * G4 + dd + 8];
            nx[mt][3] = base[(size_t)jj1 * G4 + dd + 8];
        }
    }

    __syncthreads();

    for (int hr = 0; hr < H_; ++hr) {
        // accumulators start at i2h (bias folded in)
        float acc[2][4];
        #pragma unroll
        for (int mt = 0; mt < 2; ++mt)
            #pragma unroll
            for (int i = 0; i < 4; ++i) acc[mt][i] = nx[mt][i];

        // prefetch next step's i2h (hides HBM latency under the mma work)
        {
            int hn = (hr < H_ - 1) ? hr + 1 : hr;
            const float* base = g_i2h + ((size_t)((hn * B_ + b) * W_ + wbase)) * G4;
            #pragma unroll
            for (int mt = 0; mt < 2; ++mt) {
                int dd = dbase + 16 * mt + g;
                nx[mt][0] = base[(size_t)jj0 * G4 + dd];
                nx[mt][1] = base[(size_t)jj1 * G4 + dd];
                nx[mt][2] = base[(size_t)jj0 * G4 + dd + 8];
                nx[mt][3] = base[(size_t)jj1 * G4 + dd + 8];
            }
        }

        // ---- single-pass fp16 mma GEMM over K=128 (8 ktiles) ----
        #pragma unroll
        for (int kt = 0; kt < 8; ++kt) {
            uint32_t bh[2];
            int kp = kt * 8 + t;
            bh[0] = hp[kp * 8 + g];
            bh[1] = hp[(kp + 4) * 8 + g];
            mma16816h(acc[0], (const uint32_t*)&ah[0][kt], bh);
            mma16816h(acc[1], (const uint32_t*)&ah[1][kt], bh);
        }

        // ---- write gates to smem: gt[j*516 + d] ----
        #pragma unroll
        for (int mt = 0; mt < 2; ++mt) {
            int dd = dbase + 16 * mt + g;
            gt[jj0 * 516 + dd]     = acc[mt][0];
            gt[jj1 * 516 + dd]     = acc[mt][1];
            gt[jj0 * 516 + dd + 8] = acc[mt][2];
            gt[jj1 * 516 + dd + 8] = acc[mt][3];
        }
        __syncthreads();

        // ---- cell update: 2 (col,k) pairs per thread ----
        {
            float ig = gt[j0 * 516 + k0];
            float fg = gt[j0 * 516 + k0 + 128];
            float og = gt[j0 * 516 + k0 + 256];
            float gg = gt[j0 * 516 + k0 + 384];
            cst0 = siga(fg) * cst0 + siga(ig) * tanhe(gg);
            float hv = siga(og) * tanhe(cst0);
            ((__half*)hp)[((k0 >> 1) * 8 + j0) * 2 + (k0 & 1)] = __float2half(hv);
            out[(((b * HID) + k0) * H_ + hr) * W_ + (wbase + j0)] = hv;
        }
        {
            float ig = gt[j0 * 516 + k1];
            float fg = gt[j0 * 516 + k1 + 128];
            float og = gt[j0 * 516 + k1 + 256];
            float gg = gt[j0 * 516 + k1 + 384];
            cst1 = siga(fg) * cst1 + siga(ig) * tanhe(gg);
            float hv = siga(og) * tanhe(cst1);
            ((__half*)hp)[((k1 >> 1) * 8 + j0) * 2 + (k1 & 1)] = __float2half(hv);
            out[(((b * HID) + k1) * H_ + hr) * W_ + (wbase + j0)] = hv;
        }
        __syncthreads();
    }
}

// ---------------------------------------------------------------------------
extern "C" void kernel_launch(void* const* d_in, const int* in_sizes, int n_in,
                              void* d_out, int out_size) {
    const float* x  = (const float*)d_in[0];
    const float* Wi = (const float*)d_in[1];
    const float* bi = (const float*)d_in[2];
    const float* Wh = (const float*)d_in[3];
    const float* bh = (const float*)d_in[4];
    float* out = (float*)d_out;

    static bool attr_set = false;
    if (!attr_set) {
        cudaFuncSetAttribute(conv_mma_kernel, cudaFuncAttributeMaxDynamicSharedMemorySize, CONV_SMEM);
        cudaFuncSetAttribute(lstm_kernel, cudaFuncAttributeMaxDynamicSharedMemorySize, LSTM_SMEM);
        attr_set = true;
    }

    prep_kernel<<<384, 256>>>(Wi, Wh, bi, bh);
    conv_mma_kernel<<<1024, 256, CONV_SMEM>>>(x);
    lstm_kernel<<<128, 512, LSTM_SMEM>>>(out);
}